// round 13
// baseline (speedup 1.0000x reference)
#include <cuda_runtime.h>
#include <math.h>

// ---------------------------------------------------------------------------
// SwinTransformerBlock3D — tf32 m16n8k8 everywhere; attention head-batched x3
// ---------------------------------------------------------------------------

#define LTOK (16*64*64)
#define BATCH 2
#define C 96
#define NH 6
#define HD 16
#define NW 64
#define MLPH 384
#define NTILE 2048

typedef unsigned long long u64t;

__device__ float g_ybuf[(size_t)BATCH * LTOK * C];

// ---------------- helpers --------------------------------------------------
__device__ __forceinline__ unsigned sp(const void* p) {
    return (unsigned)__cvta_generic_to_shared(p);
}
__device__ __forceinline__ u64t ldsb64(const float* p) {
    u64t v; asm volatile("ld.shared.b64 %0,[%1];" : "=l"(v) : "r"(sp(p))); return v;
}
__device__ __forceinline__ float4 ldsf4(const float* p) {
    float4 r; asm volatile("ld.shared.v4.f32 {%0,%1,%2,%3},[%4];"
                           : "=f"(r.x),"=f"(r.y),"=f"(r.z),"=f"(r.w) : "r"(sp(p))); return r;
}
__device__ __forceinline__ unsigned ldsu32(const float* p) {
    unsigned v; asm volatile("ld.shared.b32 %0,[%1];" : "=r"(v) : "r"(sp(p))); return v;
}
__device__ __forceinline__ void stsb64(float* p, u64t v) {
    asm volatile("st.shared.b64 [%0],%1;" :: "r"(sp(p)), "l"(v));
}
__device__ __forceinline__ u64t pk2(float x, float y) {
    u64t r; asm("mov.b64 %0,{%1,%2};" : "=l"(r) : "f"(x), "f"(y)); return r;
}
__device__ __forceinline__ float tf32f(float x) {
    unsigned r; asm("cvt.rna.tf32.f32 %0,%1;" : "=r"(r) : "f"(x));
    return __uint_as_float(r);
}
__device__ __forceinline__ void mma8(float* d, const unsigned* a,
                                     unsigned b0, unsigned b1) {
    asm("mma.sync.aligned.m16n8k8.row.col.f32.tf32.tf32.f32 "
        "{%0,%1,%2,%3},{%4,%5,%6,%7},{%8,%9},{%0,%1,%2,%3};"
        : "+f"(d[0]), "+f"(d[1]), "+f"(d[2]), "+f"(d[3])
        : "r"(a[0]), "r"(a[1]), "r"(a[2]), "r"(a[3]), "r"(b0), "r"(b1));
}

// ======================= Kernel A ==========================================
#define A_XS   0        // xs [64][104] tf32 LN1; reused as obuf [64][104]
#define A_Q    6656     // qbuf [64][104]
#define A_KT   13312    // kT [96][70]
#define A_V    20032    // vbuf [64][100]
#define A_S    26432    // sbuf [3][64][72] = 13824
#define A_WC   40256    // qkv chunk [32][292] (9344) / proj_w [96][100] (9600)
#define A_BIAS 49856    // 2058
#define A_REL  51914    // u16[4096] = 2048 floats
#define A_SRC  53962    // int[64]
#define A_TOT  54026    // *4 = 216104 B

__global__ __launch_bounds__(512, 1)
void win_attn_kernel(const float* __restrict__ x,
                     const float* __restrict__ g1, const float* __restrict__ b1,
                     const float* __restrict__ qkv_w, const float* __restrict__ qkv_b,
                     const float* __restrict__ proj_w, const float* __restrict__ proj_b,
                     const float* __restrict__ bias_table)
{
    extern __shared__ float smf[];
    float* xs   = smf + A_XS;
    float* qbuf = smf + A_Q;
    float* kT   = smf + A_KT;
    float* vbuf = smf + A_V;
    float* sbuf = smf + A_S;
    float* wc   = smf + A_WC;
    float* sbias = smf + A_BIAS;
    unsigned short* rel = (unsigned short*)(smf + A_REL);
    int* srcidx = (int*)(smf + A_SRC);

    const int tid = threadIdx.x;
    const int lane = tid & 31, wid = tid >> 5;
    const int g = lane >> 2, cq = lane & 3;
    const int wb = blockIdx.x;
    const int bb = wb >> 10;
    const int w  = wb & 1023;
    const int iw = w >> 8, xw = (w >> 4) & 15, tw = w & 15;

    // prefetch qkv_w chunk 0 (32x288 = 9216 floats; 18/thread, row-aligned)
    float2 wpf[9];
    {
        const float* src = qkv_w + tid * 18;
        #pragma unroll
        for (int i = 0; i < 9; i++) wpf[i] = __ldg((const float2*)(src + 2 * i));
    }

    if (tid < NW) {
        int i = tid >> 4, xx = (tid >> 2) & 3, tt = tid & 3;
        int gi = (iw * 4 + i  + 2) & 15;
        int gx = (xw * 4 + xx + 2) & 63;
        int gt = (tw * 4 + tt + 2) & 63;
        srcidx[tid] = ((gi << 6) + gx) * 64 + gt;
    }
    for (int p = tid; p < 4096; p += 512) {
        int n = p >> 6, m = p & 63;
        int di = (n >> 4)       - (m >> 4)       + 3;
        int dx = ((n >> 2) & 3) - ((m >> 2) & 3) + 3;
        int dt = (n & 3)        - (m & 3)        + 3;
        rel[p] = (unsigned short)((di * 7 + dx) * 7 + dt);
    }
    for (int i = tid; i < 343 * NH; i += 512) sbias[i] = __ldg(bias_table + i);
    __syncthreads();

    // ---- LN1 -> xs[n][104] (tf32)
    {
        const int n = tid >> 3, q8 = tid & 7;
        const float* xr = x + ((size_t)(bb * LTOK + srcidx[n])) * C + q8 * 12;
        float v[12]; float s = 0.f, ss = 0.f;
        #pragma unroll
        for (int j = 0; j < 12; j++) { float t = xr[j]; v[j] = t; s += t; ss += t * t; }
        s  += __shfl_xor_sync(0xffffffffu, s, 1);  ss += __shfl_xor_sync(0xffffffffu, ss, 1);
        s  += __shfl_xor_sync(0xffffffffu, s, 2);  ss += __shfl_xor_sync(0xffffffffu, ss, 2);
        s  += __shfl_xor_sync(0xffffffffu, s, 4);  ss += __shfl_xor_sync(0xffffffffu, ss, 4);
        float mean = s * (1.f / 96.f);
        float var  = ss * (1.f / 96.f) - mean * mean;
        float rstd = rsqrtf(var + 1e-5f);
        #pragma unroll
        for (int j = 0; j < 12; j++) {
            int c = q8 * 12 + j;
            float val = (v[j] - mean) * rstd * __ldg(g1 + c) + __ldg(b1 + c);
            xs[n * 104 + c] = tf32f(val);
        }
    }

    // ---- QKV GEMM (m16n8k8): warp = 1 m-tile x 9 n-tiles (72 cols)
    {
        const int mt = wid & 3, ng = wid >> 2;
        const int m0 = 16 * mt, n0 = 72 * ng;
        float acc[9][4];
        #pragma unroll
        for (int nt = 0; nt < 9; nt++) {
            int col = n0 + 8 * nt + 2 * cq;
            float bx = __ldg(qkv_b + col), by = __ldg(qkv_b + col + 1);
            acc[nt][0] = bx; acc[nt][1] = by;
            acc[nt][2] = bx; acc[nt][3] = by;
        }
        {   // stage chunk 0
            int kk = tid >> 4, nn = (tid & 15) * 18;
            float* d = wc + kk * 292 + nn;
            const float* pv = (const float*)wpf;
            #pragma unroll
            for (int i = 0; i < 18; i++) d[i] = tf32f(pv[i]);
        }
        __syncthreads();

        #pragma unroll 1
        for (int c3 = 0; c3 < 3; c3++) {
            if (c3 < 2) {
                const float* src = qkv_w + (c3 + 1) * 9216 + tid * 18;
                #pragma unroll
                for (int i = 0; i < 9; i++) wpf[i] = __ldg((const float2*)(src + 2 * i));
            }
            #pragma unroll
            for (int kq = 0; kq < 4; kq++) {
                const int kloc = 8 * kq + 2 * cq;
                const int kA = 32 * c3 + kloc;
                unsigned A[4];
                u64t lo = ldsb64(xs + (m0 + g) * 104 + kA);
                u64t hi = ldsb64(xs + (m0 + g + 8) * 104 + kA);
                A[0] = (unsigned)lo; A[2] = (unsigned)(lo >> 32);
                A[1] = (unsigned)hi; A[3] = (unsigned)(hi >> 32);
                #pragma unroll
                for (int nt = 0; nt < 9; nt++) {
                    const float* wp = wc + kloc * 292 + n0 + 8 * nt + g;
                    unsigned b0 = ldsu32(wp);
                    unsigned b1 = ldsu32(wp + 292);
                    mma8(acc[nt], A, b0, b1);
                }
            }
            __syncthreads();
            if (c3 < 2) {
                int kk = tid >> 4, nn = (tid & 15) * 18;
                float* d = wc + kk * 292 + nn;
                const float* pv = (const float*)wpf;
                #pragma unroll
                for (int i = 0; i < 18; i++) d[i] = tf32f(pv[i]);
                __syncthreads();
            }
        }

        // scatter fragments (tf32-rounded) to qbuf / kT / vbuf
        #pragma unroll
        for (int nt = 0; nt < 9; nt++) {
            int col = n0 + 8 * nt + 2 * cq;
            int r = m0 + g;
            if (col < 96) {
                stsb64(qbuf + r * 104 + col, pk2(tf32f(acc[nt][0]), tf32f(acc[nt][1])));
                stsb64(qbuf + (r + 8) * 104 + col, pk2(tf32f(acc[nt][2]), tf32f(acc[nt][3])));
            } else if (col < 192) {
                int kc = col - 96;
                kT[kc * 70 + r] = tf32f(acc[nt][0]);
                kT[(kc + 1) * 70 + r] = tf32f(acc[nt][1]);
                kT[kc * 70 + r + 8] = tf32f(acc[nt][2]);
                kT[(kc + 1) * 70 + r + 8] = tf32f(acc[nt][3]);
            } else {
                int vc = col - 192;
                stsb64(vbuf + r * 100 + vc, pk2(tf32f(acc[nt][0]), tf32f(acc[nt][1])));
                stsb64(vbuf + (r + 8) * 100 + vc, pk2(tf32f(acc[nt][2]), tf32f(acc[nt][3])));
            }
        }
    }
    __syncthreads();

    float* obuf = xs;   // reuse LN1 buffer for attention output

    // ---- attention: 2 batches of 3 heads
    #pragma unroll 1
    for (int h0 = 0; h0 < NH; h0 += 3) {

        // QK^T for 3 heads: 16 warps, warp = m-tile (wid&3) x 2 n-tiles (wid>>2)
        {
            const int mt2 = wid & 3, nh4 = wid >> 2;
            const int r = 16 * mt2 + g;
            #pragma unroll
            for (int h2 = 0; h2 < 3; h2++) {
                const int h = h0 + h2;
                const int hb = h * HD;
                float* sb = sbuf + h2 * 4608;
                float acc[2][4] = {{0.f,0.f,0.f,0.f},{0.f,0.f,0.f,0.f}};
                #pragma unroll
                for (int kq = 0; kq < 2; kq++) {
                    int kd = 8 * kq + 2 * cq;
                    u64t lo = ldsb64(qbuf + r * 104 + hb + kd);
                    u64t hi = ldsb64(qbuf + (r + 8) * 104 + hb + kd);
                    unsigned A[4];
                    A[0] = (unsigned)lo; A[2] = (unsigned)(lo >> 32);
                    A[1] = (unsigned)hi; A[3] = (unsigned)(hi >> 32);
                    #pragma unroll
                    for (int t = 0; t < 2; t++) {
                        int mcol = 8 * (2 * nh4 + t) + g;
                        unsigned b0 = ldsu32(kT + (hb + kd) * 70 + mcol);
                        unsigned b1 = ldsu32(kT + (hb + kd + 1) * 70 + mcol);
                        mma8(acc[t], A, b0, b1);
                    }
                }
                #pragma unroll
                for (int t = 0; t < 2; t++) {
                    int col = 8 * (2 * nh4 + t) + 2 * cq;
                    float s00 = acc[t][0] * 0.25f + sbias[rel[r * 64 + col] * NH + h];
                    float s01 = acc[t][1] * 0.25f + sbias[rel[r * 64 + col + 1] * NH + h];
                    float s10 = acc[t][2] * 0.25f + sbias[rel[(r + 8) * 64 + col] * NH + h];
                    float s11 = acc[t][3] * 0.25f + sbias[rel[(r + 8) * 64 + col + 1] * NH + h];
                    stsb64(sb + r * 72 + col, pk2(s00, s01));
                    stsb64(sb + (r + 8) * 72 + col, pk2(s10, s11));
                }
            }
        }
        __syncthreads();

        // softmax for 3 heads: row n = tid>>3, 8 cols per thread
        {
            const int n = tid >> 3, m0s = (tid & 7) * 8;
            #pragma unroll
            for (int h2 = 0; h2 < 3; h2++) {
                float* sb = sbuf + h2 * 4608;
                float4 pa = ldsf4(sb + n * 72 + m0s);
                float4 pb = ldsf4(sb + n * 72 + m0s + 4);
                float p[8] = {pa.x, pa.y, pa.z, pa.w, pb.x, pb.y, pb.z, pb.w};
                float mx = -1e30f;
                #pragma unroll
                for (int i = 0; i < 8; i++) mx = fmaxf(mx, p[i]);
                mx = fmaxf(mx, __shfl_xor_sync(0xffffffffu, mx, 1));
                mx = fmaxf(mx, __shfl_xor_sync(0xffffffffu, mx, 2));
                mx = fmaxf(mx, __shfl_xor_sync(0xffffffffu, mx, 4));
                float sum = 0.f;
                #pragma unroll
                for (int i = 0; i < 8; i++) { p[i] = __expf(p[i] - mx); sum += p[i]; }
                sum += __shfl_xor_sync(0xffffffffu, sum, 1);
                sum += __shfl_xor_sync(0xffffffffu, sum, 2);
                sum += __shfl_xor_sync(0xffffffffu, sum, 4);
                float inv = 1.f / sum;
                #pragma unroll
                for (int i = 0; i < 4; i++)
                    stsb64(sb + n * 72 + m0s + 2 * i,
                           pk2(tf32f(p[2 * i] * inv), tf32f(p[2 * i + 1] * inv)));
            }
        }
        __syncthreads();

        // AV: 24 tasks (3 heads x 4 m-tiles x 2 n-tiles) over 16 warps
        {
            #pragma unroll
            for (int tsk0 = 0; tsk0 < 2; tsk0++) {
                int t = wid + 16 * tsk0;
                if (tsk0 == 1 && wid >= 8) break;
                int h2 = t >> 3, sub = t & 7;
                int mt2 = sub >> 1, ntv = sub & 1;
                const int hb = (h0 + h2) * HD;
                float* sb = sbuf + h2 * 4608;
                const int r = 16 * mt2 + g;
                float acc[4] = {0.f, 0.f, 0.f, 0.f};
                #pragma unroll
                for (int kq = 0; kq < 8; kq++) {
                    int km = 8 * kq + 2 * cq;
                    u64t lo = ldsb64(sb + r * 72 + km);
                    u64t hi = ldsb64(sb + (r + 8) * 72 + km);
                    unsigned A[4];
                    A[0] = (unsigned)lo; A[2] = (unsigned)(lo >> 32);
                    A[1] = (unsigned)hi; A[3] = (unsigned)(hi >> 32);
                    unsigned b0 = ldsu32(vbuf + km * 100 + hb + 8 * ntv + g);
                    unsigned b1 = ldsu32(vbuf + (km + 1) * 100 + hb + 8 * ntv + g);
                    mma8(acc, A, b0, b1);
                }
                stsb64(obuf + r * 104 + hb + 8 * ntv + 2 * cq,
                       pk2(tf32f(acc[0]), tf32f(acc[1])));
                stsb64(obuf + (r + 8) * 104 + hb + 8 * ntv + 2 * cq,
                       pk2(tf32f(acc[2]), tf32f(acc[3])));
            }
        }
        __syncthreads();
    }

    // ---- stage proj_w [96][100] tf32 (one shot)
    {
        float2 t[9];
        const float* src = proj_w + tid * 18;
        #pragma unroll
        for (int i = 0; i < 9; i++) t[i] = __ldg((const float2*)(src + 2 * i));
        const float* pv = (const float*)t;
        #pragma unroll
        for (int i = 0; i < 18; i++) {
            int idx = tid * 18 + i;
            wc[(idx / 96) * 100 + (idx % 96)] = tf32f(pv[i]);
        }
    }
    __syncthreads();

    // ---- proj GEMM (m16n8k8): warp = 1 m-tile x 3 n-tiles (24 cols)
    {
        const int mt = wid & 3, ng = wid >> 2;
        const int m0 = 16 * mt, n0 = 24 * ng;
        float acc[3][4];
        #pragma unroll
        for (int nt = 0; nt < 3; nt++) {
            int col = n0 + 8 * nt + 2 * cq;
            float bx = __ldg(proj_b + col), by = __ldg(proj_b + col + 1);
            acc[nt][0] = bx; acc[nt][1] = by;
            acc[nt][2] = bx; acc[nt][3] = by;
        }
        #pragma unroll
        for (int kq = 0; kq < 12; kq++) {
            const int kloc = 8 * kq + 2 * cq;
            unsigned A[4];
            u64t lo = ldsb64(obuf + (m0 + g) * 104 + kloc);
            u64t hi = ldsb64(obuf + (m0 + g + 8) * 104 + kloc);
            A[0] = (unsigned)lo; A[2] = (unsigned)(lo >> 32);
            A[1] = (unsigned)hi; A[3] = (unsigned)(hi >> 32);
            #pragma unroll
            for (int nt = 0; nt < 3; nt++) {
                const float* wp = wc + kloc * 100 + n0 + 8 * nt + g;
                unsigned b0 = ldsu32(wp);
                unsigned b1 = ldsu32(wp + 100);
                mma8(acc[nt], A, b0, b1);
            }
        }
        int r = m0 + g;
        size_t base0 = (size_t)(bb * LTOK + srcidx[r]) * C;
        size_t base1 = (size_t)(bb * LTOK + srcidx[r + 8]) * C;
        #pragma unroll
        for (int nt = 0; nt < 3; nt++) {
            int col = n0 + 8 * nt + 2 * cq;
            float2 x0 = *(const float2*)(x + base0 + col);
            float2 x1 = *(const float2*)(x + base1 + col);
            *(float2*)(g_ybuf + base0 + col) =
                make_float2(x0.x + acc[nt][0], x0.y + acc[nt][1]);
            *(float2*)(g_ybuf + base1 + col) =
                make_float2(x1.x + acc[nt][2], x1.y + acc[nt][3]);
        }
    }
}

// ======================= Kernel B: tf32 mma MLP (R10-R12, unchanged) =======
#define SM_HID 0        // hid [64][392]                      (25088)
#define SM_H2S 25088    // h2s [64][104]                      (6656)
#define SM_W1C 31744    // w1 chunk [32][396]                 (12672)
#define SM_W2C 25088    // w2 chunk [64][396] (reuses h2s+w1c region, 25344)
#define B_TOT  50432

__global__ __launch_bounds__(512, 1)
void mlp_kernel(const float* __restrict__ g2, const float* __restrict__ b2,
                const float* __restrict__ w1, const float* __restrict__ bb1,
                const float* __restrict__ w2, const float* __restrict__ bb2,
                float* __restrict__ out)
{
    extern __shared__ float smf[];
    float* hid = smf + SM_HID;
    float* h2s = smf + SM_H2S;
    float* w1c = smf + SM_W1C;
    float* w2c = smf + SM_W2C;

    const int tid = threadIdx.x;
    const int t0 = blockIdx.x * NW;
    const int lane = tid & 31, wid = tid >> 5;
    const int g = lane >> 2, cq = lane & 3;

    float4 wpf[6];
    {
        const float* src = w1 + tid * 24;
        #pragma unroll
        for (int i = 0; i < 6; i++) wpf[i] = __ldg((const float4*)(src + 4 * i));
    }

    // ---- LN2 -> h2s[n][104]
    {
        const int n = tid >> 3, q8 = tid & 7;
        const float* yr = g_ybuf + (size_t)(t0 + n) * C + q8 * 12;
        float v[12]; float s = 0.f, ss = 0.f;
        #pragma unroll
        for (int j = 0; j < 12; j++) { float t = yr[j]; v[j] = t; s += t; ss += t * t; }
        s  += __shfl_xor_sync(0xffffffffu, s, 1);  ss += __shfl_xor_sync(0xffffffffu, ss, 1);
        s  += __shfl_xor_sync(0xffffffffu, s, 2);  ss += __shfl_xor_sync(0xffffffffu, ss, 2);
        s  += __shfl_xor_sync(0xffffffffu, s, 4);  ss += __shfl_xor_sync(0xffffffffu, ss, 4);
        float mean = s * (1.f / 96.f);
        float var  = ss * (1.f / 96.f) - mean * mean;
        float rstd = rsqrtf(var + 1e-5f);
        #pragma unroll
        for (int j = 0; j < 12; j++) {
            int c = q8 * 12 + j;
            float val = (v[j] - mean) * rstd * __ldg(g2 + c) + __ldg(b2 + c);
            h2s[n * 104 + c] = tf32f(val);
        }
    }

    // ---- GEMM1 (m16n8k8): warp = 2 m-tiles x 6 n-tiles
    const int mh = wid & 1, ng = wid >> 1;
    const int m0 = 32 * mh, n0 = 48 * ng;
    float acc1[2][6][4];
    #pragma unroll
    for (int nt = 0; nt < 6; nt++) {
        int col = n0 + 8 * nt + 2 * cq;
        float bx = __ldg(bb1 + col), by = __ldg(bb1 + col + 1);
        #pragma unroll
        for (int mi = 0; mi < 2; mi++) {
            acc1[mi][nt][0] = bx; acc1[mi][nt][1] = by;
            acc1[mi][nt][2] = bx; acc1[mi][nt][3] = by;
        }
    }
    {
        int kk = (tid * 24) / 384, nn = (tid * 24) % 384;
        float* d = w1c + kk * 396 + nn;
        const float* pv = (const float*)wpf;
        #pragma unroll
        for (int i = 0; i < 24; i++) d[i] = tf32f(pv[i]);
    }
    __syncthreads();

    #pragma unroll 1
    for (int c3 = 0; c3 < 3; c3++) {
        if (c3 < 2) {
            const float* src = w1 + (c3 + 1) * 12288 + tid * 24;
            #pragma unroll
            for (int i = 0; i < 6; i++) wpf[i] = __ldg((const float4*)(src + 4 * i));
        }
        #pragma unroll
        for (int kq = 0; kq < 4; kq++) {
            const int kb = 8 * kq;
            const int kA = 32 * c3 + kb + 2 * cq;
            unsigned A[2][4];
            #pragma unroll
            for (int mi = 0; mi < 2; mi++) {
                int row = m0 + 16 * mi + g;
                u64t lo = ldsb64(h2s + row * 104 + kA);
                u64t hi = ldsb64(h2s + (row + 8) * 104 + kA);
                A[mi][0] = (unsigned)lo; A[mi][2] = (unsigned)(lo >> 32);
                A[mi][1] = (unsigned)hi; A[mi][3] = (unsigned)(hi >> 32);
            }
            #pragma unroll
            for (int nt = 0; nt < 6; nt++) {
                const float* wp = w1c + (kb + 2 * cq) * 396 + n0 + 8 * nt + g;
                unsigned b0 = ldsu32(wp);
                unsigned b1 = ldsu32(wp + 396);
                mma8(acc1[0][nt], A[0], b0, b1);
                mma8(acc1[1][nt], A[1], b0, b1);
            }
        }
        __syncthreads();
        if (c3 < 2) {
            int kk = (tid * 24) / 384, nn = (tid * 24) % 384;
            float* d = w1c + kk * 396 + nn;
            const float* pv = (const float*)wpf;
            #pragma unroll
            for (int i = 0; i < 24; i++) d[i] = tf32f(pv[i]);
            __syncthreads();
        }
    }

    // GELU + tf32 -> hid[64][392]
    #pragma unroll
    for (int mi = 0; mi < 2; mi++) {
        #pragma unroll
        for (int nt = 0; nt < 6; nt++) {
            int row = m0 + 16 * mi + g;
            int col = n0 + 8 * nt + 2 * cq;
            float* a = acc1[mi][nt];
            float g0 = 0.5f * a[0] * (1.0f + erff(a[0] * 0.70710678118654752f));
            float g1 = 0.5f * a[1] * (1.0f + erff(a[1] * 0.70710678118654752f));
            float g2v = 0.5f * a[2] * (1.0f + erff(a[2] * 0.70710678118654752f));
            float g3 = 0.5f * a[3] * (1.0f + erff(a[3] * 0.70710678118654752f));
            stsb64(hid + row * 392 + col, pk2(tf32f(g0), tf32f(g1)));
            stsb64(hid + (row + 8) * 392 + col, pk2(tf32f(g2v), tf32f(g3)));
        }
    }

    // ---- GEMM2 (m16n8k8): 6 chunks of 64 k
    const int mt = wid & 3, n3 = wid >> 2;
    const int m0b = 16 * mt, n0b = 24 * n3;
    float acc2[3][4];
    #pragma unroll
    for (int nt = 0; nt < 3; nt++) {
        int col = n0b + 8 * nt + 2 * cq;
        float bx = __ldg(bb2 + col), by = __ldg(bb2 + col + 1);
        acc2[nt][0] = bx; acc2[nt][1] = by;
        acc2[nt][2] = bx; acc2[nt][3] = by;
    }
    float4 wpf2[3];
    {
        const float* src = w2 + tid * 12;
        #pragma unroll
        for (int i = 0; i < 3; i++) wpf2[i] = __ldg((const float4*)(src + 4 * i));
    }
    __syncthreads();

    #pragma unroll 1
    for (int ch = 0; ch < 6; ch++) {
        {
            int base = tid * 12;
            int kk = base / 96, nn = base % 96;
            float* d = w2c + kk * 396 + nn;
            const float* pv = (const float*)wpf2;
            #pragma unroll
            for (int i = 0; i < 12; i++) d[i] = tf32f(pv[i]);
        }
        __syncthreads();
        if (ch < 5) {
            const float* src = w2 + (ch + 1) * 6144 + tid * 12;
            #pragma unroll
            for (int i = 0; i < 3; i++) wpf2[i] = __ldg((const float4*)(src + 4 * i));
        }
        #pragma unroll
        for (int kq = 0; kq < 8; kq++) {
            const int kb = 8 * kq;
            const int kA = 64 * ch + kb + 2 * cq;
            unsigned A[4];
            u64t lo = ldsb64(hid + (m0b + g) * 392 + kA);
            u64t hi = ldsb64(hid + (m0b + g + 8) * 392 + kA);
            A[0] = (unsigned)lo; A[2] = (unsigned)(lo >> 32);
            A[1] = (unsigned)hi; A[3] = (unsigned)(hi >> 32);
            #pragma unroll
            for (int nt = 0; nt < 3; nt++) {
                const float* wp = w2c + (kb + 2 * cq) * 396 + n0b + 8 * nt + g;
                unsigned b0 = ldsu32(wp);
                unsigned b1 = ldsu32(wp + 396);
                mma8(acc2[nt], A, b0, b1);
            }
        }
        __syncthreads();
    }

    // epilogue: residual + store
    #pragma unroll
    for (int nt = 0; nt < 3; nt++) {
        int col = n0b + 8 * nt + 2 * cq;
        int r0 = t0 + m0b + g;
        const float2 y0 = *(const float2*)(g_ybuf + (size_t)r0 * C + col);
        const float2 y1 = *(const float2*)(g_ybuf + (size_t)(r0 + 8) * C + col);
        float2 o0 = make_float2(y0.x + acc2[nt][0], y0.y + acc2[nt][1]);
        float2 o1 = make_float2(y1.x + acc2[nt][2], y1.y + acc2[nt][3]);
        *(float2*)(out + (size_t)r0 * C + col) = o0;
        *(float2*)(out + (size_t)(r0 + 8) * C + col) = o1;
    }
}

// ---------------------------------------------------------------------------
extern "C" void kernel_launch(void* const* d_in, const int* in_sizes, int n_in,
                              void* d_out, int out_size)
{
    const float* x        = (const float*)d_in[0];
    const float* norm1_g  = (const float*)d_in[1];
    const float* norm1_b  = (const float*)d_in[2];
    const float* qkv_w    = (const float*)d_in[3];
    const float* qkv_b    = (const float*)d_in[4];
    const float* proj_w   = (const float*)d_in[5];
    const float* proj_b   = (const float*)d_in[6];
    const float* bias_tab = (const float*)d_in[7];
    const float* norm2_g  = (const float*)d_in[8];
    const float* norm2_b  = (const float*)d_in[9];
    const float* mlp_w1   = (const float*)d_in[10];
    const float* mlp_b1   = (const float*)d_in[11];
    const float* mlp_w2   = (const float*)d_in[12];
    const float* mlp_b2   = (const float*)d_in[13];
    float* out = (float*)d_out;

    cudaFuncSetAttribute(win_attn_kernel,
                         cudaFuncAttributeMaxDynamicSharedMemorySize, A_TOT * 4);
    cudaFuncSetAttribute(mlp_kernel,
                         cudaFuncAttributeMaxDynamicSharedMemorySize, B_TOT * 4);

    win_attn_kernel<<<NTILE, 512, A_TOT * 4>>>(x, norm1_g, norm1_b,
                                               qkv_w, qkv_b, proj_w, proj_b,
                                               bias_tab);
    mlp_kernel<<<NTILE, 512, B_TOT * 4>>>(norm2_g, norm2_b,
                                          mlp_w1, mlp_b1, mlp_w2, mlp_b2, out);
}

// round 14
// speedup vs baseline: 1.1798x; 1.1798x over previous
#include <cuda_runtime.h>
#include <math.h>

// ---------------------------------------------------------------------------
// SwinTransformerBlock3D — kernel A: tf32 mma (R12, proven 600us config);
// kernel B: bf16 m16n8k16 MLP (halved mma + LDS traffic)
// ---------------------------------------------------------------------------

#define LTOK (16*64*64)
#define BATCH 2
#define C 96
#define NH 6
#define HD 16
#define NW 64
#define MLPH 384
#define NTILE 2048

typedef unsigned long long u64t;

__device__ float g_ybuf[(size_t)BATCH * LTOK * C];

// ---------------- helpers --------------------------------------------------
__device__ __forceinline__ unsigned sp(const void* p) {
    return (unsigned)__cvta_generic_to_shared(p);
}
__device__ __forceinline__ u64t ldsb64(const float* p) {
    u64t v; asm volatile("ld.shared.b64 %0,[%1];" : "=l"(v) : "r"(sp(p))); return v;
}
__device__ __forceinline__ float4 ldsf4(const float* p) {
    float4 r; asm volatile("ld.shared.v4.f32 {%0,%1,%2,%3},[%4];"
                           : "=f"(r.x),"=f"(r.y),"=f"(r.z),"=f"(r.w) : "r"(sp(p))); return r;
}
__device__ __forceinline__ unsigned ldsu32(const float* p) {
    unsigned v; asm volatile("ld.shared.b32 %0,[%1];" : "=r"(v) : "r"(sp(p))); return v;
}
__device__ __forceinline__ void stsb64(float* p, u64t v) {
    asm volatile("st.shared.b64 [%0],%1;" :: "r"(sp(p)), "l"(v));
}
__device__ __forceinline__ void stsb32(float* p, unsigned v) {
    asm volatile("st.shared.b32 [%0],%1;" :: "r"(sp(p)), "r"(v));
}
__device__ __forceinline__ u64t pk2(float x, float y) {
    u64t r; asm("mov.b64 %0,{%1,%2};" : "=l"(r) : "f"(x), "f"(y)); return r;
}
__device__ __forceinline__ u64t pk2u(unsigned x, unsigned y) {
    u64t r; asm("mov.b64 %0,{%1,%2};" : "=l"(r) : "r"(x), "r"(y)); return r;
}
__device__ __forceinline__ float tf32f(float x) {
    unsigned r; asm("cvt.rna.tf32.f32 %0,%1;" : "=r"(r) : "f"(x));
    return __uint_as_float(r);
}
// pack 2 floats -> bf16x2 word: element0(lo)=x (even k), element1(hi)=y (odd k)
__device__ __forceinline__ unsigned pkbf(float x, float y) {
    unsigned r; asm("cvt.rn.bf16x2.f32 %0,%1,%2;" : "=r"(r) : "f"(y), "f"(x));
    return r;
}
__device__ __forceinline__ void mma8(float* d, const unsigned* a,
                                     unsigned b0, unsigned b1) {
    asm("mma.sync.aligned.m16n8k8.row.col.f32.tf32.tf32.f32 "
        "{%0,%1,%2,%3},{%4,%5,%6,%7},{%8,%9},{%0,%1,%2,%3};"
        : "+f"(d[0]), "+f"(d[1]), "+f"(d[2]), "+f"(d[3])
        : "r"(a[0]), "r"(a[1]), "r"(a[2]), "r"(a[3]), "r"(b0), "r"(b1));
}
__device__ __forceinline__ void mma16(float* d, const unsigned* a,
                                      unsigned b0, unsigned b1) {
    asm("mma.sync.aligned.m16n8k16.row.col.f32.bf16.bf16.f32 "
        "{%0,%1,%2,%3},{%4,%5,%6,%7},{%8,%9},{%0,%1,%2,%3};"
        : "+f"(d[0]), "+f"(d[1]), "+f"(d[2]), "+f"(d[3])
        : "r"(a[0]), "r"(a[1]), "r"(a[2]), "r"(a[3]), "r"(b0), "r"(b1));
}

// ======================= Kernel A (R12, proven) ============================
#define A_XS   0        // xs [64][104] tf32 LN1; reused as obuf [64][104]
#define A_Q    6656     // qbuf [64][104]
#define A_KT   13312    // kT [96][70]
#define A_V    20032    // vbuf [64][100]
#define A_S    26432    // sbuf [64][72]
#define A_WC   31040    // qkv chunk [32][292] / proj_w [96][100]
#define A_BIAS 40640
#define A_REL  42698
#define A_SRC  44746
#define A_TOT  44810

__global__ __launch_bounds__(512, 1)
void win_attn_kernel(const float* __restrict__ x,
                     const float* __restrict__ g1, const float* __restrict__ b1,
                     const float* __restrict__ qkv_w, const float* __restrict__ qkv_b,
                     const float* __restrict__ proj_w, const float* __restrict__ proj_b,
                     const float* __restrict__ bias_table)
{
    extern __shared__ float smf[];
    float* xs   = smf + A_XS;
    float* qbuf = smf + A_Q;
    float* kT   = smf + A_KT;
    float* vbuf = smf + A_V;
    float* sbuf = smf + A_S;
    float* wc   = smf + A_WC;
    float* sbias = smf + A_BIAS;
    unsigned short* rel = (unsigned short*)(smf + A_REL);
    int* srcidx = (int*)(smf + A_SRC);

    const int tid = threadIdx.x;
    const int lane = tid & 31, wid = tid >> 5;
    const int g = lane >> 2, cq = lane & 3;
    const int wb = blockIdx.x;
    const int bb = wb >> 10;
    const int w  = wb & 1023;
    const int iw = w >> 8, xw = (w >> 4) & 15, tw = w & 15;

    float2 wpf[9];
    {
        const float* src = qkv_w + tid * 18;
        #pragma unroll
        for (int i = 0; i < 9; i++) wpf[i] = __ldg((const float2*)(src + 2 * i));
    }

    if (tid < NW) {
        int i = tid >> 4, xx = (tid >> 2) & 3, tt = tid & 3;
        int gi = (iw * 4 + i  + 2) & 15;
        int gx = (xw * 4 + xx + 2) & 63;
        int gt = (tw * 4 + tt + 2) & 63;
        srcidx[tid] = ((gi << 6) + gx) * 64 + gt;
    }
    for (int p = tid; p < 4096; p += 512) {
        int n = p >> 6, m = p & 63;
        int di = (n >> 4)       - (m >> 4)       + 3;
        int dx = ((n >> 2) & 3) - ((m >> 2) & 3) + 3;
        int dt = (n & 3)        - (m & 3)        + 3;
        rel[p] = (unsigned short)((di * 7 + dx) * 7 + dt);
    }
    for (int i = tid; i < 343 * NH; i += 512) sbias[i] = __ldg(bias_table + i);
    __syncthreads();

    // ---- LN1 -> xs[n][104] (tf32)
    {
        const int n = tid >> 3, q8 = tid & 7;
        const float* xr = x + ((size_t)(bb * LTOK + srcidx[n])) * C + q8 * 12;
        float v[12]; float s = 0.f, ss = 0.f;
        #pragma unroll
        for (int j = 0; j < 12; j++) { float t = xr[j]; v[j] = t; s += t; ss += t * t; }
        s  += __shfl_xor_sync(0xffffffffu, s, 1);  ss += __shfl_xor_sync(0xffffffffu, ss, 1);
        s  += __shfl_xor_sync(0xffffffffu, s, 2);  ss += __shfl_xor_sync(0xffffffffu, ss, 2);
        s  += __shfl_xor_sync(0xffffffffu, s, 4);  ss += __shfl_xor_sync(0xffffffffu, ss, 4);
        float mean = s * (1.f / 96.f);
        float var  = ss * (1.f / 96.f) - mean * mean;
        float rstd = rsqrtf(var + 1e-5f);
        #pragma unroll
        for (int j = 0; j < 12; j++) {
            int c = q8 * 12 + j;
            float val = (v[j] - mean) * rstd * __ldg(g1 + c) + __ldg(b1 + c);
            xs[n * 104 + c] = tf32f(val);
        }
    }

    // ---- QKV GEMM (m16n8k8): warp = 1 m-tile x 9 n-tiles
    {
        const int mt = wid & 3, ng = wid >> 2;
        const int m0 = 16 * mt, n0 = 72 * ng;
        float acc[9][4];
        #pragma unroll
        for (int nt = 0; nt < 9; nt++) {
            int col = n0 + 8 * nt + 2 * cq;
            float bx = __ldg(qkv_b + col), by = __ldg(qkv_b + col + 1);
            acc[nt][0] = bx; acc[nt][1] = by;
            acc[nt][2] = bx; acc[nt][3] = by;
        }
        {
            int kk = tid >> 4, nn = (tid & 15) * 18;
            float* d = wc + kk * 292 + nn;
            const float* pv = (const float*)wpf;
            #pragma unroll
            for (int i = 0; i < 18; i++) d[i] = tf32f(pv[i]);
        }
        __syncthreads();

        #pragma unroll 1
        for (int c3 = 0; c3 < 3; c3++) {
            if (c3 < 2) {
                const float* src = qkv_w + (c3 + 1) * 9216 + tid * 18;
                #pragma unroll
                for (int i = 0; i < 9; i++) wpf[i] = __ldg((const float2*)(src + 2 * i));
            }
            #pragma unroll
            for (int kq = 0; kq < 4; kq++) {
                const int kloc = 8 * kq + 2 * cq;
                const int kA = 32 * c3 + kloc;
                unsigned A[4];
                u64t lo = ldsb64(xs + (m0 + g) * 104 + kA);
                u64t hi = ldsb64(xs + (m0 + g + 8) * 104 + kA);
                A[0] = (unsigned)lo; A[2] = (unsigned)(lo >> 32);
                A[1] = (unsigned)hi; A[3] = (unsigned)(hi >> 32);
                #pragma unroll
                for (int nt = 0; nt < 9; nt++) {
                    const float* wp = wc + kloc * 292 + n0 + 8 * nt + g;
                    unsigned b0 = ldsu32(wp);
                    unsigned b1 = ldsu32(wp + 292);
                    mma8(acc[nt], A, b0, b1);
                }
            }
            __syncthreads();
            if (c3 < 2) {
                int kk = tid >> 4, nn = (tid & 15) * 18;
                float* d = wc + kk * 292 + nn;
                const float* pv = (const float*)wpf;
                #pragma unroll
                for (int i = 0; i < 18; i++) d[i] = tf32f(pv[i]);
                __syncthreads();
            }
        }

        #pragma unroll
        for (int nt = 0; nt < 9; nt++) {
            int col = n0 + 8 * nt + 2 * cq;
            int r = m0 + g;
            if (col < 96) {
                stsb64(qbuf + r * 104 + col, pk2(tf32f(acc[nt][0]), tf32f(acc[nt][1])));
                stsb64(qbuf + (r + 8) * 104 + col, pk2(tf32f(acc[nt][2]), tf32f(acc[nt][3])));
            } else if (col < 192) {
                int kc = col - 96;
                kT[kc * 70 + r] = tf32f(acc[nt][0]);
                kT[(kc + 1) * 70 + r] = tf32f(acc[nt][1]);
                kT[kc * 70 + r + 8] = tf32f(acc[nt][2]);
                kT[(kc + 1) * 70 + r + 8] = tf32f(acc[nt][3]);
            } else {
                int vc = col - 192;
                stsb64(vbuf + r * 100 + vc, pk2(tf32f(acc[nt][0]), tf32f(acc[nt][1])));
                stsb64(vbuf + (r + 8) * 100 + vc, pk2(tf32f(acc[nt][2]), tf32f(acc[nt][3])));
            }
        }
    }
    __syncthreads();

    float* obuf = xs;

    // ---- attention: per head, QK^T mma -> scalar softmax -> AV mma
    #pragma unroll 1
    for (int h = 0; h < NH; h++) {
        const int hb = h * HD;

        {
            const int mt2 = wid & 3, nh4 = wid >> 2;
            const int r = 16 * mt2 + g;
            float acc[2][4] = {{0.f,0.f,0.f,0.f},{0.f,0.f,0.f,0.f}};
            #pragma unroll
            for (int kq = 0; kq < 2; kq++) {
                int kd = 8 * kq + 2 * cq;
                u64t lo = ldsb64(qbuf + r * 104 + hb + kd);
                u64t hi = ldsb64(qbuf + (r + 8) * 104 + hb + kd);
                unsigned A[4];
                A[0] = (unsigned)lo; A[2] = (unsigned)(lo >> 32);
                A[1] = (unsigned)hi; A[3] = (unsigned)(hi >> 32);
                #pragma unroll
                for (int t = 0; t < 2; t++) {
                    int mcol = 8 * (2 * nh4 + t) + g;
                    unsigned b0 = ldsu32(kT + (hb + kd) * 70 + mcol);
                    unsigned b1 = ldsu32(kT + (hb + kd + 1) * 70 + mcol);
                    mma8(acc[t], A, b0, b1);
                }
            }
            #pragma unroll
            for (int t = 0; t < 2; t++) {
                int col = 8 * (2 * nh4 + t) + 2 * cq;
                float s00 = acc[t][0] * 0.25f + sbias[rel[r * 64 + col] * NH + h];
                float s01 = acc[t][1] * 0.25f + sbias[rel[r * 64 + col + 1] * NH + h];
                float s10 = acc[t][2] * 0.25f + sbias[rel[(r + 8) * 64 + col] * NH + h];
                float s11 = acc[t][3] * 0.25f + sbias[rel[(r + 8) * 64 + col + 1] * NH + h];
                stsb64(sbuf + r * 72 + col, pk2(s00, s01));
                stsb64(sbuf + (r + 8) * 72 + col, pk2(s10, s11));
            }
        }
        __syncthreads();

        {
            const int n = tid >> 3, m0s = (tid & 7) * 8;
            float4 pa = ldsf4(sbuf + n * 72 + m0s);
            float4 pb = ldsf4(sbuf + n * 72 + m0s + 4);
            float p[8] = {pa.x, pa.y, pa.z, pa.w, pb.x, pb.y, pb.z, pb.w};
            float mx = -1e30f;
            #pragma unroll
            for (int i = 0; i < 8; i++) mx = fmaxf(mx, p[i]);
            mx = fmaxf(mx, __shfl_xor_sync(0xffffffffu, mx, 1));
            mx = fmaxf(mx, __shfl_xor_sync(0xffffffffu, mx, 2));
            mx = fmaxf(mx, __shfl_xor_sync(0xffffffffu, mx, 4));
            float sum = 0.f;
            #pragma unroll
            for (int i = 0; i < 8; i++) { p[i] = __expf(p[i] - mx); sum += p[i]; }
            sum += __shfl_xor_sync(0xffffffffu, sum, 1);
            sum += __shfl_xor_sync(0xffffffffu, sum, 2);
            sum += __shfl_xor_sync(0xffffffffu, sum, 4);
            float inv = 1.f / sum;
            #pragma unroll
            for (int i = 0; i < 4; i++)
                stsb64(sbuf + n * 72 + m0s + 2 * i,
                       pk2(tf32f(p[2 * i] * inv), tf32f(p[2 * i + 1] * inv)));
        }
        __syncthreads();

        if (wid < 8) {
            const int mt2 = wid >> 1, ntv = wid & 1;
            const int r = 16 * mt2 + g;
            float acc[4] = {0.f, 0.f, 0.f, 0.f};
            #pragma unroll
            for (int kq = 0; kq < 8; kq++) {
                int km = 8 * kq + 2 * cq;
                u64t lo = ldsb64(sbuf + r * 72 + km);
                u64t hi = ldsb64(sbuf + (r + 8) * 72 + km);
                unsigned A[4];
                A[0] = (unsigned)lo; A[2] = (unsigned)(lo >> 32);
                A[1] = (unsigned)hi; A[3] = (unsigned)(hi >> 32);
                unsigned b0 = ldsu32(vbuf + km * 100 + hb + 8 * ntv + g);
                unsigned b1 = ldsu32(vbuf + (km + 1) * 100 + hb + 8 * ntv + g);
                mma8(acc, A, b0, b1);
            }
            stsb64(obuf + r * 104 + hb + 8 * ntv + 2 * cq,
                   pk2(tf32f(acc[0]), tf32f(acc[1])));
            stsb64(obuf + (r + 8) * 104 + hb + 8 * ntv + 2 * cq,
                   pk2(tf32f(acc[2]), tf32f(acc[3])));
        }
        __syncthreads();
    }

    // ---- stage proj_w [96][100] tf32
    {
        float2 t[9];
        const float* src = proj_w + tid * 18;
        #pragma unroll
        for (int i = 0; i < 9; i++) t[i] = __ldg((const float2*)(src + 2 * i));
        const float* pv = (const float*)t;
        #pragma unroll
        for (int i = 0; i < 18; i++) {
            int idx = tid * 18 + i;
            wc[(idx / 96) * 100 + (idx % 96)] = tf32f(pv[i]);
        }
    }
    __syncthreads();

    // ---- proj GEMM + residual scatter
    {
        const int mt = wid & 3, ng = wid >> 2;
        const int m0 = 16 * mt, n0 = 24 * ng;
        float acc[3][4];
        #pragma unroll
        for (int nt = 0; nt < 3; nt++) {
            int col = n0 + 8 * nt + 2 * cq;
            float bx = __ldg(proj_b + col), by = __ldg(proj_b + col + 1);
            acc[nt][0] = bx; acc[nt][1] = by;
            acc[nt][2] = bx; acc[nt][3] = by;
        }
        #pragma unroll
        for (int kq = 0; kq < 12; kq++) {
            const int kloc = 8 * kq + 2 * cq;
            unsigned A[4];
            u64t lo = ldsb64(obuf + (m0 + g) * 104 + kloc);
            u64t hi = ldsb64(obuf + (m0 + g + 8) * 104 + kloc);
            A[0] = (unsigned)lo; A[2] = (unsigned)(lo >> 32);
            A[1] = (unsigned)hi; A[3] = (unsigned)(hi >> 32);
            #pragma unroll
            for (int nt = 0; nt < 3; nt++) {
                const float* wp = wc + kloc * 100 + n0 + 8 * nt + g;
                unsigned b0 = ldsu32(wp);
                unsigned b1 = ldsu32(wp + 100);
                mma8(acc[nt], A, b0, b1);
            }
        }
        int r = m0 + g;
        size_t base0 = (size_t)(bb * LTOK + srcidx[r]) * C;
        size_t base1 = (size_t)(bb * LTOK + srcidx[r + 8]) * C;
        #pragma unroll
        for (int nt = 0; nt < 3; nt++) {
            int col = n0 + 8 * nt + 2 * cq;
            float2 x0 = *(const float2*)(x + base0 + col);
            float2 x1 = *(const float2*)(x + base1 + col);
            *(float2*)(g_ybuf + base0 + col) =
                make_float2(x0.x + acc[nt][0], x0.y + acc[nt][1]);
            *(float2*)(g_ybuf + base1 + col) =
                make_float2(x1.x + acc[nt][2], x1.y + acc[nt][3]);
        }
    }
}

// ======================= Kernel B: bf16 m16n8k16 MLP =======================
// word layouts (1 word = 1 float slot = bf16x2 pair along k):
//   hid [64][196]  (192 used)    offset 0
//   h2b [64][52]   (48 used)     offset 12544
//   w1c [16][396]  (384 used)    offset 15872   (pairs x cols)
//   w2c [32][100]  (96 used)     offset 12544   (reuses h2b region)
#define SM_HID 0
#define SM_H2B 12544
#define SM_W1C 15872
#define SM_W2C 12544
#define B_TOT  22208

__global__ __launch_bounds__(512, 1)
void mlp_kernel(const float* __restrict__ g2, const float* __restrict__ b2,
                const float* __restrict__ w1, const float* __restrict__ bb1,
                const float* __restrict__ w2, const float* __restrict__ bb2,
                float* __restrict__ out)
{
    extern __shared__ float smf[];
    float* hid = smf + SM_HID;
    float* h2b = smf + SM_H2B;
    float* w1c = smf + SM_W1C;
    float* w2c = smf + SM_W2C;

    const int tid = threadIdx.x;
    const int t0 = blockIdx.x * NW;
    const int lane = tid & 31, wid = tid >> 5;
    const int g = lane >> 2, cq = lane & 3;

    // prefetch w1 chunk 0: pair p = tid>>5, cols nn..nn+11 of rows 2p, 2p+1
    const int w1p = tid >> 5, w1n = (tid & 31) * 12;
    float4 wpf[6];
    {
        const float* ra = w1 + (2 * w1p) * MLPH + w1n;
        const float* rb = w1 + (2 * w1p + 1) * MLPH + w1n;
        #pragma unroll
        for (int i = 0; i < 3; i++) wpf[i] = __ldg((const float4*)(ra + 4 * i));
        #pragma unroll
        for (int i = 0; i < 3; i++) wpf[3 + i] = __ldg((const float4*)(rb + 4 * i));
    }

    // ---- LN2 -> h2b[n][52] bf16x2 words (pairs along C)
    {
        const int n = tid >> 3, q8 = tid & 7;
        const float* yr = g_ybuf + (size_t)(t0 + n) * C + q8 * 12;
        float v[12]; float s = 0.f, ss = 0.f;
        #pragma unroll
        for (int j = 0; j < 12; j++) { float t = yr[j]; v[j] = t; s += t; ss += t * t; }
        s  += __shfl_xor_sync(0xffffffffu, s, 1);  ss += __shfl_xor_sync(0xffffffffu, ss, 1);
        s  += __shfl_xor_sync(0xffffffffu, s, 2);  ss += __shfl_xor_sync(0xffffffffu, ss, 2);
        s  += __shfl_xor_sync(0xffffffffu, s, 4);  ss += __shfl_xor_sync(0xffffffffu, ss, 4);
        float mean = s * (1.f / 96.f);
        float var  = ss * (1.f / 96.f) - mean * mean;
        float rstd = rsqrtf(var + 1e-5f);
        float hv[12];
        #pragma unroll
        for (int j = 0; j < 12; j++) {
            int c = q8 * 12 + j;
            hv[j] = (v[j] - mean) * rstd * __ldg(g2 + c) + __ldg(b2 + c);
        }
        #pragma unroll
        for (int i = 0; i < 6; i += 2)
            stsb64(h2b + n * 52 + q8 * 6 + i,
                   pk2u(pkbf(hv[2 * i], hv[2 * i + 1]),
                        pkbf(hv[2 * i + 2], hv[2 * i + 3])));
    }

    // ---- GEMM1 (m16n8k16): warp = 2 m-tiles x 6 n-tiles
    const int mh = wid & 1, ng = wid >> 1;
    const int m0 = 32 * mh, n0 = 48 * ng;
    float acc1[2][6][4];
    #pragma unroll
    for (int nt = 0; nt < 6; nt++) {
        int col = n0 + 8 * nt + 2 * cq;
        float bx = __ldg(bb1 + col), by = __ldg(bb1 + col + 1);
        #pragma unroll
        for (int mi = 0; mi < 2; mi++) {
            acc1[mi][nt][0] = bx; acc1[mi][nt][1] = by;
            acc1[mi][nt][2] = bx; acc1[mi][nt][3] = by;
        }
    }
    {   // stage chunk 0: w1c[p][nn..nn+11] = pkbf(rowA, rowB)
        const float* ra = (const float*)wpf;
        const float* rb = (const float*)(wpf + 3);
        float* d = w1c + w1p * 396 + w1n;
        #pragma unroll
        for (int i = 0; i < 12; i += 2)
            stsb64(d + i, pk2u(pkbf(ra[i], rb[i]), pkbf(ra[i + 1], rb[i + 1])));
    }
    __syncthreads();

    #pragma unroll 1
    for (int c3 = 0; c3 < 3; c3++) {
        if (c3 < 2) {
            const float* ra = w1 + (32 * (c3 + 1) + 2 * w1p) * MLPH + w1n;
            const float* rb = ra + MLPH;
            #pragma unroll
            for (int i = 0; i < 3; i++) wpf[i] = __ldg((const float4*)(ra + 4 * i));
            #pragma unroll
            for (int i = 0; i < 3; i++) wpf[3 + i] = __ldg((const float4*)(rb + 4 * i));
        }
        #pragma unroll
        for (int kq = 0; kq < 2; kq++) {
            const int ploc = 8 * kq + 2 * cq;         // local pair in chunk
            const int pA = 16 * c3 + ploc;            // global pair in h2b
            unsigned A[2][4];
            #pragma unroll
            for (int mi = 0; mi < 2; mi++) {
                int row = m0 + 16 * mi + g;
                u64t lo = ldsb64(h2b + row * 52 + pA);
                u64t hi = ldsb64(h2b + (row + 8) * 52 + pA);
                A[mi][0] = (unsigned)lo; A[mi][2] = (unsigned)(lo >> 32);
                A[mi][1] = (unsigned)hi; A[mi][3] = (unsigned)(hi >> 32);
            }
            #pragma unroll
            for (int nt = 0; nt < 6; nt++) {
                const float* wp = w1c + ploc * 396 + n0 + 8 * nt + g;
                unsigned b0 = ldsu32(wp);
                unsigned b1 = ldsu32(wp + 396);
                mma16(acc1[0][nt], A[0], b0, b1);
                mma16(acc1[1][nt], A[1], b0, b1);
            }
        }
        __syncthreads();
        if (c3 < 2) {
            const float* ra = (const float*)wpf;
            const float* rb = (const float*)(wpf + 3);
            float* d = w1c + w1p * 396 + w1n;
            #pragma unroll
            for (int i = 0; i < 12; i += 2)
                stsb64(d + i, pk2u(pkbf(ra[i], rb[i]), pkbf(ra[i + 1], rb[i + 1])));
            __syncthreads();
        }
    }

    // GELU -> hid bf16x2 words (pairs along hidden dim)
    #pragma unroll
    for (int mi = 0; mi < 2; mi++) {
        #pragma unroll
        for (int nt = 0; nt < 6; nt++) {
            int row = m0 + 16 * mi + g;
            int wrd = n0 / 2 + 4 * nt + cq;
            float* a = acc1[mi][nt];
            float g0 = 0.5f * a[0] * (1.0f + erff(a[0] * 0.70710678118654752f));
            float g1 = 0.5f * a[1] * (1.0f + erff(a[1] * 0.70710678118654752f));
            float g2v = 0.5f * a[2] * (1.0f + erff(a[2] * 0.70710678118654752f));
            float g3 = 0.5f * a[3] * (1.0f + erff(a[3] * 0.70710678118654752f));
            stsb32(hid + row * 196 + wrd, pkbf(g0, g1));
            stsb32(hid + (row + 8) * 196 + wrd, pkbf(g2v, g3));
        }
    }

    // ---- GEMM2 (m16n8k16): 6 chunks of 32 pairs (=64 k)
    const int mt = wid & 3, n3 = wid >> 2;
    const int m0b = 16 * mt, n0b = 24 * n3;
    float acc2[3][4];
    #pragma unroll
    for (int nt = 0; nt < 3; nt++) {
        int col = n0b + 8 * nt + 2 * cq;
        float bx = __ldg(bb2 + col), by = __ldg(bb2 + col + 1);
        acc2[nt][0] = bx; acc2[nt][1] = by;
        acc2[nt][2] = bx; acc2[nt][3] = by;
    }
    // prefetch w2 chunk 0: pair p = tid>>4, cols nn..nn+5 of rows 2p, 2p+1
    const int w2p = tid >> 4, w2n = (tid & 15) * 6;
    float2 wpf2[6];
    {
        const float* ra = w2 + (2 * w2p) * 96 + w2n;
        const float* rb = ra + 96;
        #pragma unroll
        for (int i = 0; i < 3; i++) wpf2[i] = __ldg((const float2*)(ra + 2 * i));
        #pragma unroll
        for (int i = 0; i < 3; i++) wpf2[3 + i] = __ldg((const float2*)(rb + 2 * i));
    }
    __syncthreads();   // all warps done with w1c/h2b; hid fully written

    #pragma unroll 1
    for (int ch = 0; ch < 6; ch++) {
        {   // stage chunk ch
            const float* ra = (const float*)wpf2;
            const float* rb = (const float*)(wpf2 + 3);
            float* d = w2c + w2p * 100 + w2n;
            #pragma unroll
            for (int i = 0; i < 6; i += 2)
                stsb64(d + i, pk2u(pkbf(ra[i], rb[i]), pkbf(ra[i + 1], rb[i + 1])));
        }
        __syncthreads();
        if (ch < 5) {
            const float* ra = w2 + (64 * (ch + 1) + 2 * w2p) * 96 + w2n;
            const float* rb = ra + 96;
            #pragma unroll
            for (int i = 0; i < 3; i++) wpf2[i] = __ldg((const float2*)(ra + 2 * i));
            #pragma unroll
            for (int i = 0; i < 3; i++) wpf2[3 + i] = __ldg((const float2*)(rb + 2 * i));
        }
        #pragma unroll
        for (int kq = 0; kq < 4; kq++) {
            const int ploc = 8 * kq + 2 * cq;         // local pair in chunk
            const int pA = 32 * ch + ploc;            // global pair in hid
            unsigned A[4];
            u64t lo = ldsb64(hid + (m0b + g) * 196 + pA);
            u64t hi = ldsb64(hid + (m0b + g + 8) * 196 + pA);
            A[0] = (unsigned)lo; A[2] = (unsigned)(lo >> 32);
            A[1] = (unsigned)hi; A[3] = (unsigned)(hi >> 32);
            #pragma unroll
            for (int nt = 0; nt < 3; nt++) {
                const float* wp = w2c + ploc * 100 + n0b + 8 * nt + g;
                unsigned b0 = ldsu32(wp);
                unsigned b1 = ldsu32(wp + 100);
                mma16(acc2[nt], A, b0, b1);
            }
        }
        __syncthreads();
    }

    // epilogue: residual + store
    #pragma unroll
    for (int nt = 0; nt < 3; nt++) {
        int col = n0b + 8 * nt + 2 * cq;
        int r0 = t0 + m0b + g;
        const float2 y0 = *(const float2*)(g_ybuf + (size_t)r0 * C + col);
        const float2 y1 = *(const float2*)(g_ybuf + (size_t)(r0 + 8) * C + col);
        float2 o0 = make_float2(y0.x + acc2[nt][0], y0.y + acc2[nt][1]);
        float2 o1 = make_float2(y1.x + acc2[nt][2], y1.y + acc2[nt][3]);
        *(float2*)(out + (size_t)r0 * C + col) = o0;
        *(float2*)(out + (size_t)(r0 + 8) * C + col) = o1;
    }
}

// ---------------------------------------------------------------------------
extern "C" void kernel_launch(void* const* d_in, const int* in_sizes, int n_in,
                              void* d_out, int out_size)
{
    const float* x        = (const float*)d_in[0];
    const float* norm1_g  = (const float*)d_in[1];
    const float* norm1_b  = (const float*)d_in[2];
    const float* qkv_w    = (const float*)d_in[3];
    const float* qkv_b    = (const float*)d_in[4];
    const float* proj_w   = (const float*)d_in[5];
    const float* proj_b   = (const float*)d_in[6];
    const float* bias_tab = (const float*)d_in[7];
    const float* norm2_g  = (const float*)d_in[8];
    const float* norm2_b  = (const float*)d_in[9];
    const float* mlp_w1   = (const float*)d_in[10];
    const float* mlp_b1   = (const float*)d_in[11];
    const float* mlp_w2   = (const float*)d_in[12];
    const float* mlp_b2   = (const float*)d_in[13];
    float* out = (float*)d_out;

    cudaFuncSetAttribute(win_attn_kernel,
                         cudaFuncAttributeMaxDynamicSharedMemorySize, A_TOT * 4);
    cudaFuncSetAttribute(mlp_kernel,
                         cudaFuncAttributeMaxDynamicSharedMemorySize, B_TOT * 4);

    win_attn_kernel<<<NTILE, 512, A_TOT * 4>>>(x, norm1_g, norm1_b,
                                               qkv_w, qkv_b, proj_w, proj_b,
                                               bias_tab);
    mlp_kernel<<<NTILE, 512, B_TOT * 4>>>(norm2_g, norm2_b,
                                          mlp_w1, mlp_b1, mlp_w2, mlp_b2, out);
}

// round 16
// speedup vs baseline: 1.2743x; 1.0801x over previous
#include <cuda_runtime.h>
#include <math.h>

// ---------------------------------------------------------------------------
// SwinTransformerBlock3D — bf16 m16n8k16 for QKV/proj/MLP; tf32 attention core
// ---------------------------------------------------------------------------

#define LTOK (16*64*64)
#define BATCH 2
#define C 96
#define NH 6
#define HD 16
#define NW 64
#define MLPH 384
#define NTILE 2048

typedef unsigned long long u64t;

__device__ float g_ybuf[(size_t)BATCH * LTOK * C];

// ---------------- helpers --------------------------------------------------
__device__ __forceinline__ unsigned sp(const void* p) {
    return (unsigned)__cvta_generic_to_shared(p);
}
__device__ __forceinline__ u64t ldsb64(const float* p) {
    u64t v; asm volatile("ld.shared.b64 %0,[%1];" : "=l"(v) : "r"(sp(p))); return v;
}
__device__ __forceinline__ float4 ldsf4(const float* p) {
    float4 r; asm volatile("ld.shared.v4.f32 {%0,%1,%2,%3},[%4];"
                           : "=f"(r.x),"=f"(r.y),"=f"(r.z),"=f"(r.w) : "r"(sp(p))); return r;
}
__device__ __forceinline__ unsigned ldsu32(const float* p) {
    unsigned v; asm volatile("ld.shared.b32 %0,[%1];" : "=r"(v) : "r"(sp(p))); return v;
}
__device__ __forceinline__ void stsb64(float* p, u64t v) {
    asm volatile("st.shared.b64 [%0],%1;" :: "r"(sp(p)), "l"(v));
}
__device__ __forceinline__ void stsb32(float* p, unsigned v) {
    asm volatile("st.shared.b32 [%0],%1;" :: "r"(sp(p)), "r"(v));
}
__device__ __forceinline__ u64t pk2(float x, float y) {
    u64t r; asm("mov.b64 %0,{%1,%2};" : "=l"(r) : "f"(x), "f"(y)); return r;
}
__device__ __forceinline__ u64t pk2u(unsigned x, unsigned y) {
    u64t r; asm("mov.b64 %0,{%1,%2};" : "=l"(r) : "r"(x), "r"(y)); return r;
}
__device__ __forceinline__ float tf32f(float x) {
    unsigned r; asm("cvt.rna.tf32.f32 %0,%1;" : "=r"(r) : "f"(x));
    return __uint_as_float(r);
}
// pack 2 floats -> bf16x2 word: element0(lo)=x (even k), element1(hi)=y (odd k)
__device__ __forceinline__ unsigned pkbf(float x, float y) {
    unsigned r; asm("cvt.rn.bf16x2.f32 %0,%1,%2;" : "=r"(r) : "f"(y), "f"(x));
    return r;
}
__device__ __forceinline__ void mma8(float* d, const unsigned* a,
                                     unsigned b0, unsigned b1) {
    asm("mma.sync.aligned.m16n8k8.row.col.f32.tf32.tf32.f32 "
        "{%0,%1,%2,%3},{%4,%5,%6,%7},{%8,%9},{%0,%1,%2,%3};"
        : "+f"(d[0]), "+f"(d[1]), "+f"(d[2]), "+f"(d[3])
        : "r"(a[0]), "r"(a[1]), "r"(a[2]), "r"(a[3]), "r"(b0), "r"(b1));
}
__device__ __forceinline__ void mma16(float* d, const unsigned* a,
                                      unsigned b0, unsigned b1) {
    asm("mma.sync.aligned.m16n8k16.row.col.f32.bf16.bf16.f32 "
        "{%0,%1,%2,%3},{%4,%5,%6,%7},{%8,%9},{%0,%1,%2,%3};"
        : "+f"(d[0]), "+f"(d[1]), "+f"(d[2]), "+f"(d[3])
        : "r"(a[0]), "r"(a[1]), "r"(a[2]), "r"(a[3]), "r"(b0), "r"(b1));
}

// ======================= Kernel A ==========================================
// word layouts:
//   xb   [64][52]  bf16x2 LN1 pairs; reused as obuf [64][52] bf16x2
//   qbuf [64][104] fp32(tf32)   kT [96][70]   vbuf [64][100]   sbuf [64][72]
//   wcb  QKV chunk [16][292] bf16x2 / proj [48][100] bf16x2
#define A_XB   0        // 3328
#define A_Q    3328     // 6656
#define A_KT   9984     // 6720
#define A_V    16704    // 6400
#define A_S    23104    // 4608
#define A_WC   27712    // 4800
#define A_BIAS 32512    // 2058
#define A_REL  34570    // 2048
#define A_SRC  36618    // 64
#define A_TOT  36682

__global__ __launch_bounds__(512, 1)
void win_attn_kernel(const float* __restrict__ x,
                     const float* __restrict__ g1, const float* __restrict__ b1,
                     const float* __restrict__ qkv_w, const float* __restrict__ qkv_b,
                     const float* __restrict__ proj_w, const float* __restrict__ proj_b,
                     const float* __restrict__ bias_table)
{
    extern __shared__ float smf[];
    float* xb   = smf + A_XB;
    float* qbuf = smf + A_Q;
    float* kT   = smf + A_KT;
    float* vbuf = smf + A_V;
    float* sbuf = smf + A_S;
    float* wcb  = smf + A_WC;
    float* sbias = smf + A_BIAS;
    unsigned short* rel = (unsigned short*)(smf + A_REL);
    int* srcidx = (int*)(smf + A_SRC);

    const int tid = threadIdx.x;
    const int lane = tid & 31, wid = tid >> 5;
    const int g = lane >> 2, cq = lane & 3;
    const int wb = blockIdx.x;
    const int bb = wb >> 10;
    const int w  = wb & 1023;
    const int iw = w >> 8, xw = (w >> 4) & 15, tw = w & 15;

    // prefetch QKV weight chunk 0: pair p = tid>>5, cols (tid&31)*9 .. +8
    // of rows 2p and 2p+1 (chunk = 32 k-rows = 16 pairs x 288 cols)
    // NOTE: 9-float stride is only 4-byte aligned -> scalar loads only.
    const int qwp = tid >> 5, qwn = (tid & 31) * 9;
    float ra[9], rb[9];
    {
        const float* pa = qkv_w + (2 * qwp) * 288 + qwn;
        const float* pb = pa + 288;
        #pragma unroll
        for (int i = 0; i < 9; i++) ra[i] = __ldg(pa + i);
        #pragma unroll
        for (int i = 0; i < 9; i++) rb[i] = __ldg(pb + i);
    }

    if (tid < NW) {
        int i = tid >> 4, xx = (tid >> 2) & 3, tt = tid & 3;
        int gi = (iw * 4 + i  + 2) & 15;
        int gx = (xw * 4 + xx + 2) & 63;
        int gt = (tw * 4 + tt + 2) & 63;
        srcidx[tid] = ((gi << 6) + gx) * 64 + gt;
    }
    for (int p = tid; p < 4096; p += 512) {
        int n = p >> 6, m = p & 63;
        int di = (n >> 4)       - (m >> 4)       + 3;
        int dx = ((n >> 2) & 3) - ((m >> 2) & 3) + 3;
        int dt = (n & 3)        - (m & 3)        + 3;
        rel[p] = (unsigned short)((di * 7 + dx) * 7 + dt);
    }
    for (int i = tid; i < 343 * NH; i += 512) sbias[i] = __ldg(bias_table + i);
    __syncthreads();

    // ---- LN1 -> xb[n][52] bf16x2 pairs along C
    {
        const int n = tid >> 3, q8 = tid & 7;
        const float* xr = x + ((size_t)(bb * LTOK + srcidx[n])) * C + q8 * 12;
        float v[12]; float s = 0.f, ss = 0.f;
        #pragma unroll
        for (int j = 0; j < 12; j++) { float t = xr[j]; v[j] = t; s += t; ss += t * t; }
        s  += __shfl_xor_sync(0xffffffffu, s, 1);  ss += __shfl_xor_sync(0xffffffffu, ss, 1);
        s  += __shfl_xor_sync(0xffffffffu, s, 2);  ss += __shfl_xor_sync(0xffffffffu, ss, 2);
        s  += __shfl_xor_sync(0xffffffffu, s, 4);  ss += __shfl_xor_sync(0xffffffffu, ss, 4);
        float mean = s * (1.f / 96.f);
        float var  = ss * (1.f / 96.f) - mean * mean;
        float rstd = rsqrtf(var + 1e-5f);
        float hv[12];
        #pragma unroll
        for (int j = 0; j < 12; j++) {
            int c = q8 * 12 + j;
            hv[j] = (v[j] - mean) * rstd * __ldg(g1 + c) + __ldg(b1 + c);
        }
        #pragma unroll
        for (int i = 0; i < 6; i += 2)
            stsb64(xb + n * 52 + q8 * 6 + i,
                   pk2u(pkbf(hv[2 * i], hv[2 * i + 1]),
                        pkbf(hv[2 * i + 2], hv[2 * i + 3])));
    }

    // ---- QKV GEMM (m16n8k16): warp = 1 m-tile x 9 n-tiles; 3 chunks x 2 kq
    {
        const int mt = wid & 3, ng = wid >> 2;
        const int m0 = 16 * mt, n0 = 72 * ng;
        float acc[9][4];
        #pragma unroll
        for (int nt = 0; nt < 9; nt++) {
            int col = n0 + 8 * nt + 2 * cq;
            float bx = __ldg(qkv_b + col), by = __ldg(qkv_b + col + 1);
            acc[nt][0] = bx; acc[nt][1] = by;
            acc[nt][2] = bx; acc[nt][3] = by;
        }
        {   // stage chunk 0
            float* d = wcb + qwp * 292 + qwn;
            #pragma unroll
            for (int i = 0; i < 9; i++) stsb32(d + i, pkbf(ra[i], rb[i]));
        }
        __syncthreads();

        #pragma unroll 1
        for (int c3 = 0; c3 < 3; c3++) {
            if (c3 < 2) {
                const float* pa = qkv_w + (32 * (c3 + 1) + 2 * qwp) * 288 + qwn;
                const float* pb = pa + 288;
                #pragma unroll
                for (int i = 0; i < 9; i++) ra[i] = __ldg(pa + i);
                #pragma unroll
                for (int i = 0; i < 9; i++) rb[i] = __ldg(pb + i);
            }
            #pragma unroll
            for (int kq = 0; kq < 2; kq++) {
                const int ploc = 8 * kq + 2 * cq;
                const int pA = 16 * c3 + ploc;
                unsigned A[4];
                u64t lo = ldsb64(xb + (m0 + g) * 52 + pA);
                u64t hi = ldsb64(xb + (m0 + g + 8) * 52 + pA);
                A[0] = (unsigned)lo; A[2] = (unsigned)(lo >> 32);
                A[1] = (unsigned)hi; A[3] = (unsigned)(hi >> 32);
                #pragma unroll
                for (int nt = 0; nt < 9; nt++) {
                    const float* wp = wcb + ploc * 292 + n0 + 8 * nt + g;
                    unsigned b0 = ldsu32(wp);
                    unsigned b1 = ldsu32(wp + 292);
                    mma16(acc[nt], A, b0, b1);
                }
            }
            __syncthreads();
            if (c3 < 2) {
                float* d = wcb + qwp * 292 + qwn;
                #pragma unroll
                for (int i = 0; i < 9; i++) stsb32(d + i, pkbf(ra[i], rb[i]));
                __syncthreads();
            }
        }

        // scatter fragments (tf32-rounded) to qbuf / kT / vbuf (fp32 attention)
        #pragma unroll
        for (int nt = 0; nt < 9; nt++) {
            int col = n0 + 8 * nt + 2 * cq;
            int r = m0 + g;
            if (col < 96) {
                stsb64(qbuf + r * 104 + col, pk2(tf32f(acc[nt][0]), tf32f(acc[nt][1])));
                stsb64(qbuf + (r + 8) * 104 + col, pk2(tf32f(acc[nt][2]), tf32f(acc[nt][3])));
            } else if (col < 192) {
                int kc = col - 96;
                kT[kc * 70 + r] = tf32f(acc[nt][0]);
                kT[(kc + 1) * 70 + r] = tf32f(acc[nt][1]);
                kT[kc * 70 + r + 8] = tf32f(acc[nt][2]);
                kT[(kc + 1) * 70 + r + 8] = tf32f(acc[nt][3]);
            } else {
                int vc = col - 192;
                stsb64(vbuf + r * 100 + vc, pk2(tf32f(acc[nt][0]), tf32f(acc[nt][1])));
                stsb64(vbuf + (r + 8) * 100 + vc, pk2(tf32f(acc[nt][2]), tf32f(acc[nt][3])));
            }
        }
    }
    __syncthreads();

    float* obuf = xb;   // reuse: attention output as bf16x2 pairs along C

    // ---- attention (tf32 core, unchanged): QK^T mma -> softmax -> AV mma
    #pragma unroll 1
    for (int h = 0; h < NH; h++) {
        const int hb = h * HD;

        {
            const int mt2 = wid & 3, nh4 = wid >> 2;
            const int r = 16 * mt2 + g;
            float acc[2][4] = {{0.f,0.f,0.f,0.f},{0.f,0.f,0.f,0.f}};
            #pragma unroll
            for (int kq = 0; kq < 2; kq++) {
                int kd = 8 * kq + 2 * cq;
                u64t lo = ldsb64(qbuf + r * 104 + hb + kd);
                u64t hi = ldsb64(qbuf + (r + 8) * 104 + hb + kd);
                unsigned A[4];
                A[0] = (unsigned)lo; A[2] = (unsigned)(lo >> 32);
                A[1] = (unsigned)hi; A[3] = (unsigned)(hi >> 32);
                #pragma unroll
                for (int t = 0; t < 2; t++) {
                    int mcol = 8 * (2 * nh4 + t) + g;
                    unsigned b0 = ldsu32(kT + (hb + kd) * 70 + mcol);
                    unsigned b1 = ldsu32(kT + (hb + kd + 1) * 70 + mcol);
                    mma8(acc[t], A, b0, b1);
                }
            }
            #pragma unroll
            for (int t = 0; t < 2; t++) {
                int col = 8 * (2 * nh4 + t) + 2 * cq;
                float s00 = acc[t][0] * 0.25f + sbias[rel[r * 64 + col] * NH + h];
                float s01 = acc[t][1] * 0.25f + sbias[rel[r * 64 + col + 1] * NH + h];
                float s10 = acc[t][2] * 0.25f + sbias[rel[(r + 8) * 64 + col] * NH + h];
                float s11 = acc[t][3] * 0.25f + sbias[rel[(r + 8) * 64 + col + 1] * NH + h];
                stsb64(sbuf + r * 72 + col, pk2(s00, s01));
                stsb64(sbuf + (r + 8) * 72 + col, pk2(s10, s11));
            }
        }
        __syncthreads();

        {
            const int n = tid >> 3, m0s = (tid & 7) * 8;
            float4 pa = ldsf4(sbuf + n * 72 + m0s);
            float4 pb = ldsf4(sbuf + n * 72 + m0s + 4);
            float p[8] = {pa.x, pa.y, pa.z, pa.w, pb.x, pb.y, pb.z, pb.w};
            float mx = -1e30f;
            #pragma unroll
            for (int i = 0; i < 8; i++) mx = fmaxf(mx, p[i]);
            mx = fmaxf(mx, __shfl_xor_sync(0xffffffffu, mx, 1));
            mx = fmaxf(mx, __shfl_xor_sync(0xffffffffu, mx, 2));
            mx = fmaxf(mx, __shfl_xor_sync(0xffffffffu, mx, 4));
            float sum = 0.f;
            #pragma unroll
            for (int i = 0; i < 8; i++) { p[i] = __expf(p[i] - mx); sum += p[i]; }
            sum += __shfl_xor_sync(0xffffffffu, sum, 1);
            sum += __shfl_xor_sync(0xffffffffu, sum, 2);
            sum += __shfl_xor_sync(0xffffffffu, sum, 4);
            float inv = 1.f / sum;
            #pragma unroll
            for (int i = 0; i < 4; i++)
                stsb64(sbuf + n * 72 + m0s + 2 * i,
                       pk2(tf32f(p[2 * i] * inv), tf32f(p[2 * i + 1] * inv)));
        }
        __syncthreads();

        if (wid < 8) {
            const int mt2 = wid >> 1, ntv = wid & 1;
            const int r = 16 * mt2 + g;
            float acc[4] = {0.f, 0.f, 0.f, 0.f};
            #pragma unroll
            for (int kq = 0; kq < 8; kq++) {
                int km = 8 * kq + 2 * cq;
                u64t lo = ldsb64(sbuf + r * 72 + km);
                u64t hi = ldsb64(sbuf + (r + 8) * 72 + km);
                unsigned A[4];
                A[0] = (unsigned)lo; A[2] = (unsigned)(lo >> 32);
                A[1] = (unsigned)hi; A[3] = (unsigned)(hi >> 32);
                unsigned b0 = ldsu32(vbuf + km * 100 + hb + 8 * ntv + g);
                unsigned b1 = ldsu32(vbuf + (km + 1) * 100 + hb + 8 * ntv + g);
                mma8(acc, A, b0, b1);
            }
            // pack adjacent-d pair directly as bf16x2 word into obuf
            stsb32(obuf + r * 52 + 8 * h + 4 * ntv + cq, pkbf(acc[0], acc[1]));
            stsb32(obuf + (r + 8) * 52 + 8 * h + 4 * ntv + cq, pkbf(acc[2], acc[3]));
        }
        __syncthreads();
    }

    // ---- stage proj_w -> wcb [48 pairs][100] bf16x2 (one shot)
    {
        #pragma unroll
        for (int i = 0; i < 9; i++) {
            int idx = tid * 9 + i;
            int p = idx / 96, col = idx - 96 * p;
            float wa = __ldg(proj_w + (2 * p) * 96 + col);
            float wbv = __ldg(proj_w + (2 * p + 1) * 96 + col);
            stsb32(wcb + p * 100 + col, pkbf(wa, wbv));
        }
    }
    __syncthreads();

    // ---- proj GEMM (m16n8k16): warp = 1 m-tile x 3 n-tiles; kq 0..5
    {
        const int mt = wid & 3, ng = wid >> 2;
        const int m0 = 16 * mt, n0 = 24 * ng;
        float acc[3][4];
        #pragma unroll
        for (int nt = 0; nt < 3; nt++) {
            int col = n0 + 8 * nt + 2 * cq;
            float bx = __ldg(proj_b + col), by = __ldg(proj_b + col + 1);
            acc[nt][0] = bx; acc[nt][1] = by;
            acc[nt][2] = bx; acc[nt][3] = by;
        }
        #pragma unroll
        for (int kq = 0; kq < 6; kq++) {
            const int ploc = 8 * kq + 2 * cq;
            unsigned A[4];
            u64t lo = ldsb64(obuf + (m0 + g) * 52 + ploc);
            u64t hi = ldsb64(obuf + (m0 + g + 8) * 52 + ploc);
            A[0] = (unsigned)lo; A[2] = (unsigned)(lo >> 32);
            A[1] = (unsigned)hi; A[3] = (unsigned)(hi >> 32);
            #pragma unroll
            for (int nt = 0; nt < 3; nt++) {
                const float* wp = wcb + ploc * 100 + n0 + 8 * nt + g;
                unsigned b0 = ldsu32(wp);
                unsigned b1 = ldsu32(wp + 100);
                mma16(acc[nt], A, b0, b1);
            }
        }
        int r = m0 + g;
        size_t base0 = (size_t)(bb * LTOK + srcidx[r]) * C;
        size_t base1 = (size_t)(bb * LTOK + srcidx[r + 8]) * C;
        #pragma unroll
        for (int nt = 0; nt < 3; nt++) {
            int col = n0 + 8 * nt + 2 * cq;
            float2 x0 = *(const float2*)(x + base0 + col);
            float2 x1 = *(const float2*)(x + base1 + col);
            *(float2*)(g_ybuf + base0 + col) =
                make_float2(x0.x + acc[nt][0], x0.y + acc[nt][1]);
            *(float2*)(g_ybuf + base1 + col) =
                make_float2(x1.x + acc[nt][2], x1.y + acc[nt][3]);
        }
    }
}

// ======================= Kernel B: bf16 m16n8k16 MLP (R14, unchanged) ======
#define SM_HID 0
#define SM_H2B 12544
#define SM_W1C 15872
#define SM_W2C 12544
#define B_TOT  22208

__global__ __launch_bounds__(512, 1)
void mlp_kernel(const float* __restrict__ g2, const float* __restrict__ b2,
                const float* __restrict__ w1, const float* __restrict__ bb1,
                const float* __restrict__ w2, const float* __restrict__ bb2,
                float* __restrict__ out)
{
    extern __shared__ float smf[];
    float* hid = smf + SM_HID;
    float* h2b = smf + SM_H2B;
    float* w1c = smf + SM_W1C;
    float* w2c = smf + SM_W2C;

    const int tid = threadIdx.x;
    const int t0 = blockIdx.x * NW;
    const int lane = tid & 31, wid = tid >> 5;
    const int g = lane >> 2, cq = lane & 3;

    const int w1p = tid >> 5, w1n = (tid & 31) * 12;
    float4 wpf[6];
    {
        const float* ra = w1 + (2 * w1p) * MLPH + w1n;
        const float* rb = w1 + (2 * w1p + 1) * MLPH + w1n;
        #pragma unroll
        for (int i = 0; i < 3; i++) wpf[i] = __ldg((const float4*)(ra + 4 * i));
        #pragma unroll
        for (int i = 0; i < 3; i++) wpf[3 + i] = __ldg((const float4*)(rb + 4 * i));
    }

    // ---- LN2 -> h2b[n][52] bf16x2 words
    {
        const int n = tid >> 3, q8 = tid & 7;
        const float* yr = g_ybuf + (size_t)(t0 + n) * C + q8 * 12;
        float v[12]; float s = 0.f, ss = 0.f;
        #pragma unroll
        for (int j = 0; j < 12; j++) { float t = yr[j]; v[j] = t; s += t; ss += t * t; }
        s  += __shfl_xor_sync(0xffffffffu, s, 1);  ss += __shfl_xor_sync(0xffffffffu, ss, 1);
        s  += __shfl_xor_sync(0xffffffffu, s, 2);  ss += __shfl_xor_sync(0xffffffffu, ss, 2);
        s  += __shfl_xor_sync(0xffffffffu, s, 4);  ss += __shfl_xor_sync(0xffffffffu, ss, 4);
        float mean = s * (1.f / 96.f);
        float var  = ss * (1.f / 96.f) - mean * mean;
        float rstd = rsqrtf(var + 1e-5f);
        float hv[12];
        #pragma unroll
        for (int j = 0; j < 12; j++) {
            int c = q8 * 12 + j;
            hv[j] = (v[j] - mean) * rstd * __ldg(g2 + c) + __ldg(b2 + c);
        }
        #pragma unroll
        for (int i = 0; i < 6; i += 2)
            stsb64(h2b + n * 52 + q8 * 6 + i,
                   pk2u(pkbf(hv[2 * i], hv[2 * i + 1]),
                        pkbf(hv[2 * i + 2], hv[2 * i + 3])));
    }

    // ---- GEMM1 (m16n8k16): warp = 2 m-tiles x 6 n-tiles
    const int mh = wid & 1, ng = wid >> 1;
    const int m0 = 32 * mh, n0 = 48 * ng;
    float acc1[2][6][4];
    #pragma unroll
    for (int nt = 0; nt < 6; nt++) {
        int col = n0 + 8 * nt + 2 * cq;
        float bx = __ldg(bb1 + col), by = __ldg(bb1 + col + 1);
        #pragma unroll
        for (int mi = 0; mi < 2; mi++) {
            acc1[mi][nt][0] = bx; acc1[mi][nt][1] = by;
            acc1[mi][nt][2] = bx; acc1[mi][nt][3] = by;
        }
    }
    {
        const float* ra = (const float*)wpf;
        const float* rb = (const float*)(wpf + 3);
        float* d = w1c + w1p * 396 + w1n;
        #pragma unroll
        for (int i = 0; i < 12; i += 2)
            stsb64(d + i, pk2u(pkbf(ra[i], rb[i]), pkbf(ra[i + 1], rb[i + 1])));
    }
    __syncthreads();

    #pragma unroll 1
    for (int c3 = 0; c3 < 3; c3++) {
        if (c3 < 2) {
            const float* ra = w1 + (32 * (c3 + 1) + 2 * w1p) * MLPH + w1n;
            const float* rb = ra + MLPH;
            #pragma unroll
            for (int i = 0; i < 3; i++) wpf[i] = __ldg((const float4*)(ra + 4 * i));
            #pragma unroll
            for (int i = 0; i < 3; i++) wpf[3 + i] = __ldg((const float4*)(rb + 4 * i));
        }
        #pragma unroll
        for (int kq = 0; kq < 2; kq++) {
            const int ploc = 8 * kq + 2 * cq;
            const int pA = 16 * c3 + ploc;
            unsigned A[2][4];
            #pragma unroll
            for (int mi = 0; mi < 2; mi++) {
                int row = m0 + 16 * mi + g;
                u64t lo = ldsb64(h2b + row * 52 + pA);
                u64t hi = ldsb64(h2b + (row + 8) * 52 + pA);
                A[mi][0] = (unsigned)lo; A[mi][2] = (unsigned)(lo >> 32);
                A[mi][1] = (unsigned)hi; A[mi][3] = (unsigned)(hi >> 32);
            }
            #pragma unroll
            for (int nt = 0; nt < 6; nt++) {
                const float* wp = w1c + ploc * 396 + n0 + 8 * nt + g;
                unsigned b0 = ldsu32(wp);
                unsigned b1 = ldsu32(wp + 396);
                mma16(acc1[0][nt], A[0], b0, b1);
                mma16(acc1[1][nt], A[1], b0, b1);
            }
        }
        __syncthreads();
        if (c3 < 2) {
            const float* ra = (const float*)wpf;
            const float* rb = (const float*)(wpf + 3);
            float* d = w1c + w1p * 396 + w1n;
            #pragma unroll
            for (int i = 0; i < 12; i += 2)
                stsb64(d + i, pk2u(pkbf(ra[i], rb[i]), pkbf(ra[i + 1], rb[i + 1])));
            __syncthreads();
        }
    }

    // GELU -> hid bf16x2
    #pragma unroll
    for (int mi = 0; mi < 2; mi++) {
        #pragma unroll
        for (int nt = 0; nt < 6; nt++) {
            int row = m0 + 16 * mi + g;
            int wrd = n0 / 2 + 4 * nt + cq;
            float* a = acc1[mi][nt];
            float g0 = 0.5f * a[0] * (1.0f + erff(a[0] * 0.70710678118654752f));
            float g1 = 0.5f * a[1] * (1.0f + erff(a[1] * 0.70710678118654752f));
            float g2v = 0.5f * a[2] * (1.0f + erff(a[2] * 0.70710678118654752f));
            float g3 = 0.5f * a[3] * (1.0f + erff(a[3] * 0.70710678118654752f));
            stsb32(hid + row * 196 + wrd, pkbf(g0, g1));
            stsb32(hid + (row + 8) * 196 + wrd, pkbf(g2v, g3));
        }
    }

    // ---- GEMM2 (m16n8k16): 6 chunks of 32 pairs
    const int mt = wid & 3, n3 = wid >> 2;
    const int m0b = 16 * mt, n0b = 24 * n3;
    float acc2[3][4];
    #pragma unroll
    for (int nt = 0; nt < 3; nt++) {
        int col = n0b + 8 * nt + 2 * cq;
        float bx = __ldg(bb2 + col), by = __ldg(bb2 + col + 1);
        acc2[nt][0] = bx; acc2[nt][1] = by;
        acc2[nt][2] = bx; acc2[nt][3] = by;
    }
    const int w2p = tid >> 4, w2n = (tid & 15) * 6;
    float2 wpf2[6];
    {
        const float* ra = w2 + (2 * w2p) * 96 + w2n;
        const float* rb = ra + 96;
        #pragma unroll
        for (int i = 0; i < 3; i++) wpf2[i] = __ldg((const float2*)(ra + 2 * i));
        #pragma unroll
        for (int i = 0; i < 3; i++) wpf2[3 + i] = __ldg((const float2*)(rb + 2 * i));
    }
    __syncthreads();

    #pragma unroll 1
    for (int ch = 0; ch < 6; ch++) {
        {
            const float* ra = (const float*)wpf2;
            const float* rb = (const float*)(wpf2 + 3);
            float* d = w2c + w2p * 100 + w2n;
            #pragma unroll
            for (int i = 0; i < 6; i += 2)
                stsb64(d + i, pk2u(pkbf(ra[i], rb[i]), pkbf(ra[i + 1], rb[i + 1])));
        }
        __syncthreads();
        if (ch < 5) {
            const float* ra = w2 + (64 * (ch + 1) + 2 * w2p) * 96 + w2n;
            const float* rb = ra + 96;
            #pragma unroll
            for (int i = 0; i < 3; i++) wpf2[i] = __ldg((const float2*)(ra + 2 * i));
            #pragma unroll
            for (int i = 0; i < 3; i++) wpf2[3 + i] = __ldg((const float2*)(rb + 2 * i));
        }
        #pragma unroll
        for (int kq = 0; kq < 4; kq++) {
            const int ploc = 8 * kq + 2 * cq;
            const int pA = 32 * ch + ploc;
            unsigned A[4];
            u64t lo = ldsb64(hid + (m0b + g) * 196 + pA);
            u64t hi = ldsb64(hid + (m0b + g + 8) * 196 + pA);
            A[0] = (unsigned)lo; A[2] = (unsigned)(lo >> 32);
            A[1] = (unsigned)hi; A[3] = (unsigned)(hi >> 32);
            #pragma unroll
            for (int nt = 0; nt < 3; nt++) {
                const float* wp = w2c + ploc * 100 + n0b + 8 * nt + g;
                unsigned b0 = ldsu32(wp);
                unsigned b1 = ldsu32(wp + 100);
                mma16(acc2[nt], A, b0, b1);
            }
        }
        __syncthreads();
    }

    // epilogue: residual + store
    #pragma unroll
    for (int nt = 0; nt < 3; nt++) {
        int col = n0b + 8 * nt + 2 * cq;
        int r0 = t0 + m0b + g;
        const float2 y0 = *(const float2*)(g_ybuf + (size_t)r0 * C + col);
        const float2 y1 = *(const float2*)(g_ybuf + (size_t)(r0 + 8) * C + col);
        float2 o0 = make_float2(y0.x + acc2[nt][0], y0.y + acc2[nt][1]);
        float2 o1 = make_float2(y1.x + acc2[nt][2], y1.y + acc2[nt][3]);
        *(float2*)(out + (size_t)r0 * C + col) = o0;
        *(float2*)(out + (size_t)(r0 + 8) * C + col) = o1;
    }
}

// ---------------------------------------------------------------------------
extern "C" void kernel_launch(void* const* d_in, const int* in_sizes, int n_in,
                              void* d_out, int out_size)
{
    const float* x        = (const float*)d_in[0];
    const float* norm1_g  = (const float*)d_in[1];
    const float* norm1_b  = (const float*)d_in[2];
    const float* qkv_w    = (const float*)d_in[3];
    const float* qkv_b    = (const float*)d_in[4];
    const float* proj_w   = (const float*)d_in[5];
    const float* proj_b   = (const float*)d_in[6];
    const float* bias_tab = (const float*)d_in[7];
    const float* norm2_g  = (const float*)d_in[8];
    const float* norm2_b  = (const float*)d_in[9];
    const float* mlp_w1   = (const float*)d_in[10];
    const float* mlp_b1   = (const float*)d_in[11];
    const float* mlp_w2   = (const float*)d_in[12];
    const float* mlp_b2   = (const float*)d_in[13];
    float* out = (float*)d_out;

    cudaFuncSetAttribute(win_attn_kernel,
                         cudaFuncAttributeMaxDynamicSharedMemorySize, A_TOT * 4);
    cudaFuncSetAttribute(mlp_kernel,
                         cudaFuncAttributeMaxDynamicSharedMemorySize, B_TOT * 4);

    win_attn_kernel<<<NTILE, 512, A_TOT * 4>>>(x, norm1_g, norm1_b,
                                               qkv_w, qkv_b, proj_w, proj_b,
                                               bias_tab);
    mlp_kernel<<<NTILE, 512, B_TOT * 4>>>(norm2_g, norm2_b,
                                          mlp_w1, mlp_b1, mlp_w2, mlp_b2, out);
}

// round 17
// speedup vs baseline: 1.3433x; 1.0542x over previous
#include <cuda_runtime.h>
#include <math.h>

// ---------------------------------------------------------------------------
// SwinTransformerBlock3D — bf16 m16n8k16 everywhere (QKV/attn/proj/MLP)
// ---------------------------------------------------------------------------

#define LTOK (16*64*64)
#define BATCH 2
#define C 96
#define NH 6
#define HD 16
#define NW 64
#define MLPH 384
#define NTILE 2048

typedef unsigned long long u64t;

__device__ float g_ybuf[(size_t)BATCH * LTOK * C];

// ---------------- helpers --------------------------------------------------
__device__ __forceinline__ unsigned sp(const void* p) {
    return (unsigned)__cvta_generic_to_shared(p);
}
__device__ __forceinline__ u64t ldsb64(const float* p) {
    u64t v; asm volatile("ld.shared.b64 %0,[%1];" : "=l"(v) : "r"(sp(p))); return v;
}
__device__ __forceinline__ float4 ldsf4(const float* p) {
    float4 r; asm volatile("ld.shared.v4.f32 {%0,%1,%2,%3},[%4];"
                           : "=f"(r.x),"=f"(r.y),"=f"(r.z),"=f"(r.w) : "r"(sp(p))); return r;
}
__device__ __forceinline__ unsigned ldsu32(const float* p) {
    unsigned v; asm volatile("ld.shared.b32 %0,[%1];" : "=r"(v) : "r"(sp(p))); return v;
}
__device__ __forceinline__ float ldsf32(const float* p) {
    float v; asm volatile("ld.shared.f32 %0,[%1];" : "=f"(v) : "r"(sp(p))); return v;
}
__device__ __forceinline__ void stsb64(float* p, u64t v) {
    asm volatile("st.shared.b64 [%0],%1;" :: "r"(sp(p)), "l"(v));
}
__device__ __forceinline__ void stsb32(float* p, unsigned v) {
    asm volatile("st.shared.b32 [%0],%1;" :: "r"(sp(p)), "r"(v));
}
__device__ __forceinline__ u64t pk2(float x, float y) {
    u64t r; asm("mov.b64 %0,{%1,%2};" : "=l"(r) : "f"(x), "f"(y)); return r;
}
__device__ __forceinline__ u64t pk2u(unsigned x, unsigned y) {
    u64t r; asm("mov.b64 %0,{%1,%2};" : "=l"(r) : "r"(x), "r"(y)); return r;
}
// pack 2 floats -> bf16x2 word: element0(lo)=x (even k), element1(hi)=y (odd k)
__device__ __forceinline__ unsigned pkbf(float x, float y) {
    unsigned r; asm("cvt.rn.bf16x2.f32 %0,%1,%2;" : "=r"(r) : "f"(y), "f"(x));
    return r;
}
__device__ __forceinline__ void mma16(float* d, const unsigned* a,
                                      unsigned b0, unsigned b1) {
    asm("mma.sync.aligned.m16n8k16.row.col.f32.bf16.bf16.f32 "
        "{%0,%1,%2,%3},{%4,%5,%6,%7},{%8,%9},{%0,%1,%2,%3};"
        : "+f"(d[0]), "+f"(d[1]), "+f"(d[2]), "+f"(d[3])
        : "r"(a[0]), "r"(a[1]), "r"(a[2]), "r"(a[3]), "r"(b0), "r"(b1));
}

// ======================= Kernel A ==========================================
// word layouts:
//   xb   [64][52]  bf16x2 LN1 pairs; reused as obuf [64][52] bf16x2
//   qb   [64][28]  bf16x2 q d-pairs (24 used)
//   kbT  [48][68]  bf16x2 k d-pairs, transposed (pair x key)
//   vbuf [64][100] fp32 v scatter; vb [32][100] bf16x2 token-pairs
//   sbuf [64][72]  fp32 scores / bf16x2 P pairs (words 0..31)
//   wcb  QKV chunk [16][292] bf16x2 / proj [48][100] bf16x2
#define A_XB   0        // 3328
#define A_QB   3328     // 1792
#define A_KB   5120     // 3264
#define A_V    8384     // 6400
#define A_VB   14784    // 3200
#define A_S    17984    // 4608
#define A_WC   22592    // 4800
#define A_BIAS 27392    // 2058
#define A_REL  29450    // 2048
#define A_SRC  31498    // 64
#define A_TOT  31562

__global__ __launch_bounds__(512, 1)
void win_attn_kernel(const float* __restrict__ x,
                     const float* __restrict__ g1, const float* __restrict__ b1,
                     const float* __restrict__ qkv_w, const float* __restrict__ qkv_b,
                     const float* __restrict__ proj_w, const float* __restrict__ proj_b,
                     const float* __restrict__ bias_table)
{
    extern __shared__ float smf[];
    float* xb   = smf + A_XB;
    float* qb   = smf + A_QB;
    float* kbT  = smf + A_KB;
    float* vbuf = smf + A_V;
    float* vb   = smf + A_VB;
    float* sbuf = smf + A_S;
    float* wcb  = smf + A_WC;
    float* sbias = smf + A_BIAS;
    unsigned short* rel = (unsigned short*)(smf + A_REL);
    int* srcidx = (int*)(smf + A_SRC);

    const int tid = threadIdx.x;
    const int lane = tid & 31, wid = tid >> 5;
    const int g = lane >> 2, cq = lane & 3;
    const int wb = blockIdx.x;
    const int bb = wb >> 10;
    const int w  = wb & 1023;
    const int iw = w >> 8, xw = (w >> 4) & 15, tw = w & 15;

    // prefetch QKV weight chunk 0 (scalar loads: 9-float stride is 4B-aligned)
    const int qwp = tid >> 5, qwn = (tid & 31) * 9;
    float ra[9], rb[9];
    {
        const float* pa = qkv_w + (2 * qwp) * 288 + qwn;
        const float* pb = pa + 288;
        #pragma unroll
        for (int i = 0; i < 9; i++) ra[i] = __ldg(pa + i);
        #pragma unroll
        for (int i = 0; i < 9; i++) rb[i] = __ldg(pb + i);
    }

    if (tid < NW) {
        int i = tid >> 4, xx = (tid >> 2) & 3, tt = tid & 3;
        int gi = (iw * 4 + i  + 2) & 15;
        int gx = (xw * 4 + xx + 2) & 63;
        int gt = (tw * 4 + tt + 2) & 63;
        srcidx[tid] = ((gi << 6) + gx) * 64 + gt;
    }
    for (int p = tid; p < 4096; p += 512) {
        int n = p >> 6, m = p & 63;
        int di = (n >> 4)       - (m >> 4)       + 3;
        int dx = ((n >> 2) & 3) - ((m >> 2) & 3) + 3;
        int dt = (n & 3)        - (m & 3)        + 3;
        rel[p] = (unsigned short)((di * 7 + dx) * 7 + dt);
    }
    for (int i = tid; i < 343 * NH; i += 512) sbias[i] = __ldg(bias_table + i);
    __syncthreads();

    // ---- LN1 -> xb[n][52] bf16x2 pairs along C
    {
        const int n = tid >> 3, q8 = tid & 7;
        const float* xr = x + ((size_t)(bb * LTOK + srcidx[n])) * C + q8 * 12;
        float v[12]; float s = 0.f, ss = 0.f;
        #pragma unroll
        for (int j = 0; j < 12; j++) { float t = xr[j]; v[j] = t; s += t; ss += t * t; }
        s  += __shfl_xor_sync(0xffffffffu, s, 1);  ss += __shfl_xor_sync(0xffffffffu, ss, 1);
        s  += __shfl_xor_sync(0xffffffffu, s, 2);  ss += __shfl_xor_sync(0xffffffffu, ss, 2);
        s  += __shfl_xor_sync(0xffffffffu, s, 4);  ss += __shfl_xor_sync(0xffffffffu, ss, 4);
        float mean = s * (1.f / 96.f);
        float var  = ss * (1.f / 96.f) - mean * mean;
        float rstd = rsqrtf(var + 1e-5f);
        float hv[12];
        #pragma unroll
        for (int j = 0; j < 12; j++) {
            int c = q8 * 12 + j;
            hv[j] = (v[j] - mean) * rstd * __ldg(g1 + c) + __ldg(b1 + c);
        }
        #pragma unroll
        for (int i = 0; i < 6; i += 2)
            stsb64(xb + n * 52 + q8 * 6 + i,
                   pk2u(pkbf(hv[2 * i], hv[2 * i + 1]),
                        pkbf(hv[2 * i + 2], hv[2 * i + 3])));
    }

    // ---- QKV GEMM (m16n8k16): warp = 1 m-tile x 9 n-tiles; 3 chunks x 2 kq
    {
        const int mt = wid & 3, ng = wid >> 2;
        const int m0 = 16 * mt, n0 = 72 * ng;
        float acc[9][4];
        #pragma unroll
        for (int nt = 0; nt < 9; nt++) {
            int col = n0 + 8 * nt + 2 * cq;
            float bx = __ldg(qkv_b + col), by = __ldg(qkv_b + col + 1);
            acc[nt][0] = bx; acc[nt][1] = by;
            acc[nt][2] = bx; acc[nt][3] = by;
        }
        {   // stage chunk 0
            float* d = wcb + qwp * 292 + qwn;
            #pragma unroll
            for (int i = 0; i < 9; i++) stsb32(d + i, pkbf(ra[i], rb[i]));
        }
        __syncthreads();

        #pragma unroll 1
        for (int c3 = 0; c3 < 3; c3++) {
            if (c3 < 2) {
                const float* pa = qkv_w + (32 * (c3 + 1) + 2 * qwp) * 288 + qwn;
                const float* pb = pa + 288;
                #pragma unroll
                for (int i = 0; i < 9; i++) ra[i] = __ldg(pa + i);
                #pragma unroll
                for (int i = 0; i < 9; i++) rb[i] = __ldg(pb + i);
            }
            #pragma unroll
            for (int kq = 0; kq < 2; kq++) {
                const int ploc = 8 * kq + 2 * cq;
                const int pA = 16 * c3 + ploc;
                unsigned A[4];
                u64t lo = ldsb64(xb + (m0 + g) * 52 + pA);
                u64t hi = ldsb64(xb + (m0 + g + 8) * 52 + pA);
                A[0] = (unsigned)lo; A[2] = (unsigned)(lo >> 32);
                A[1] = (unsigned)hi; A[3] = (unsigned)(hi >> 32);
                #pragma unroll
                for (int nt = 0; nt < 9; nt++) {
                    const float* wp = wcb + ploc * 292 + n0 + 8 * nt + g;
                    unsigned b0 = ldsu32(wp);
                    unsigned b1 = ldsu32(wp + 292);
                    mma16(acc[nt], A, b0, b1);
                }
            }
            __syncthreads();
            if (c3 < 2) {
                float* d = wcb + qwp * 292 + qwn;
                #pragma unroll
                for (int i = 0; i < 9; i++) stsb32(d + i, pkbf(ra[i], rb[i]));
                __syncthreads();
            }
        }

        // scatter fragments: q/k as bf16 d-pairs, v as fp32
        #pragma unroll
        for (int nt = 0; nt < 9; nt++) {
            int col = n0 + 8 * nt + 2 * cq;
            int r = m0 + g;
            if (col < 96) {
                int cp = col >> 1;
                stsb32(qb + r * 28 + cp, pkbf(acc[nt][0], acc[nt][1]));
                stsb32(qb + (r + 8) * 28 + cp, pkbf(acc[nt][2], acc[nt][3]));
            } else if (col < 192) {
                int kp = (col - 96) >> 1;
                stsb32(kbT + kp * 68 + r, pkbf(acc[nt][0], acc[nt][1]));
                stsb32(kbT + kp * 68 + r + 8, pkbf(acc[nt][2], acc[nt][3]));
            } else {
                int vc = col - 192;
                stsb64(vbuf + r * 100 + vc, pk2(acc[nt][0], acc[nt][1]));
                stsb64(vbuf + (r + 8) * 100 + vc, pk2(acc[nt][2], acc[nt][3]));
            }
        }
    }
    __syncthreads();

    // ---- repack V -> vb[32 token-pairs][100] bf16x2
    {
        const int p = tid >> 4, d0 = (tid & 15) * 6;
        const float* va = vbuf + (2 * p) * 100 + d0;
        const float* vbp = va + 100;
        float* d = vb + p * 100 + d0;
        #pragma unroll
        for (int i = 0; i < 6; i++)
            stsb32(d + i, pkbf(ldsf32(va + i), ldsf32(vbp + i)));
    }
    __syncthreads();

    float* obuf = xb;   // reuse: attention output as bf16x2 pairs along C

    // ---- attention: bf16 QK^T -> fp32 softmax -> bf16 AV
    #pragma unroll 1
    for (int h = 0; h < NH; h++) {
        const int hb = h * HD;
        const int hp = h * 8;       // d-pair base for this head

        // QK^T: 16 warps, warp = m-tile (wid&3) x 2 n-tiles (wid>>2); 1 mma16 each
        {
            const int mt2 = wid & 3, nh4 = wid >> 2;
            const int r = 16 * mt2 + g;
            float acc[2][4] = {{0.f,0.f,0.f,0.f},{0.f,0.f,0.f,0.f}};
            unsigned A[4];
            u64t lo = ldsb64(qb + r * 28 + hp + 2 * cq);
            u64t hi = ldsb64(qb + (r + 8) * 28 + hp + 2 * cq);
            A[0] = (unsigned)lo; A[2] = (unsigned)(lo >> 32);
            A[1] = (unsigned)hi; A[3] = (unsigned)(hi >> 32);
            #pragma unroll
            for (int t = 0; t < 2; t++) {
                int mcol = 8 * (2 * nh4 + t) + g;
                unsigned b0 = ldsu32(kbT + (hp + 2 * cq) * 68 + mcol);
                unsigned b1 = ldsu32(kbT + (hp + 2 * cq + 1) * 68 + mcol);
                mma16(acc[t], A, b0, b1);
            }
            #pragma unroll
            for (int t = 0; t < 2; t++) {
                int col = 8 * (2 * nh4 + t) + 2 * cq;
                float s00 = acc[t][0] * 0.25f + sbias[rel[r * 64 + col] * NH + h];
                float s01 = acc[t][1] * 0.25f + sbias[rel[r * 64 + col + 1] * NH + h];
                float s10 = acc[t][2] * 0.25f + sbias[rel[(r + 8) * 64 + col] * NH + h];
                float s11 = acc[t][3] * 0.25f + sbias[rel[(r + 8) * 64 + col + 1] * NH + h];
                stsb64(sbuf + r * 72 + col, pk2(s00, s01));
                stsb64(sbuf + (r + 8) * 72 + col, pk2(s10, s11));
            }
        }
        __syncthreads();

        // softmax: row n = tid>>3, 8 cols; write P as bf16 m-pairs (words 0..31)
        {
            const int n = tid >> 3, q8 = tid & 7;
            const int m0s = q8 * 8;
            float4 pa = ldsf4(sbuf + n * 72 + m0s);
            float4 pb = ldsf4(sbuf + n * 72 + m0s + 4);
            float p[8] = {pa.x, pa.y, pa.z, pa.w, pb.x, pb.y, pb.z, pb.w};
            float mx = -1e30f;
            #pragma unroll
            for (int i = 0; i < 8; i++) mx = fmaxf(mx, p[i]);
            mx = fmaxf(mx, __shfl_xor_sync(0xffffffffu, mx, 1));
            mx = fmaxf(mx, __shfl_xor_sync(0xffffffffu, mx, 2));
            mx = fmaxf(mx, __shfl_xor_sync(0xffffffffu, mx, 4));
            float sum = 0.f;
            #pragma unroll
            for (int i = 0; i < 8; i++) { p[i] = __expf(p[i] - mx); sum += p[i]; }
            sum += __shfl_xor_sync(0xffffffffu, sum, 1);
            sum += __shfl_xor_sync(0xffffffffu, sum, 2);
            sum += __shfl_xor_sync(0xffffffffu, sum, 4);
            float inv = 1.f / sum;
            stsb64(sbuf + n * 72 + 4 * q8,
                   pk2u(pkbf(p[0] * inv, p[1] * inv), pkbf(p[2] * inv, p[3] * inv)));
            stsb64(sbuf + n * 72 + 4 * q8 + 2,
                   pk2u(pkbf(p[4] * inv, p[5] * inv), pkbf(p[6] * inv, p[7] * inv)));
        }
        __syncthreads();

        // AV: warps 0..7, warp = m-tile (wid>>1) x n-tile (wid&1); 4 mma16
        if (wid < 8) {
            const int mt2 = wid >> 1, ntv = wid & 1;
            const int r = 16 * mt2 + g;
            float acc[4] = {0.f, 0.f, 0.f, 0.f};
            #pragma unroll
            for (int kq = 0; kq < 4; kq++) {
                int ploc = 8 * kq + 2 * cq;
                u64t lo = ldsb64(sbuf + r * 72 + ploc);
                u64t hi = ldsb64(sbuf + (r + 8) * 72 + ploc);
                unsigned A[4];
                A[0] = (unsigned)lo; A[2] = (unsigned)(lo >> 32);
                A[1] = (unsigned)hi; A[3] = (unsigned)(hi >> 32);
                unsigned b0 = ldsu32(vb + ploc * 100 + hb + 8 * ntv + g);
                unsigned b1 = ldsu32(vb + (ploc + 1) * 100 + hb + 8 * ntv + g);
                mma16(acc, A, b0, b1);
            }
            stsb32(obuf + r * 52 + 8 * h + 4 * ntv + cq, pkbf(acc[0], acc[1]));
            stsb32(obuf + (r + 8) * 52 + 8 * h + 4 * ntv + cq, pkbf(acc[2], acc[3]));
        }
        __syncthreads();
    }

    // ---- stage proj_w -> wcb [48 pairs][100] bf16x2 (one shot)
    {
        #pragma unroll
        for (int i = 0; i < 9; i++) {
            int idx = tid * 9 + i;
            int p = idx / 96, col = idx - 96 * p;
            float wa = __ldg(proj_w + (2 * p) * 96 + col);
            float wbv = __ldg(proj_w + (2 * p + 1) * 96 + col);
            stsb32(wcb + p * 100 + col, pkbf(wa, wbv));
        }
    }
    __syncthreads();

    // ---- proj GEMM (m16n8k16): warp = 1 m-tile x 3 n-tiles; kq 0..5
    {
        const int mt = wid & 3, ng = wid >> 2;
        const int m0 = 16 * mt, n0 = 24 * ng;
        float acc[3][4];
        #pragma unroll
        for (int nt = 0; nt < 3; nt++) {
            int col = n0 + 8 * nt + 2 * cq;
            float bx = __ldg(proj_b + col), by = __ldg(proj_b + col + 1);
            acc[nt][0] = bx; acc[nt][1] = by;
            acc[nt][2] = bx; acc[nt][3] = by;
        }
        #pragma unroll
        for (int kq = 0; kq < 6; kq++) {
            const int ploc = 8 * kq + 2 * cq;
            unsigned A[4];
            u64t lo = ldsb64(obuf + (m0 + g) * 52 + ploc);
            u64t hi = ldsb64(obuf + (m0 + g + 8) * 52 + ploc);
            A[0] = (unsigned)lo; A[2] = (unsigned)(lo >> 32);
            A[1] = (unsigned)hi; A[3] = (unsigned)(hi >> 32);
            #pragma unroll
            for (int nt = 0; nt < 3; nt++) {
                const float* wp = wcb + ploc * 100 + n0 + 8 * nt + g;
                unsigned b0 = ldsu32(wp);
                unsigned b1 = ldsu32(wp + 100);
                mma16(acc[nt], A, b0, b1);
            }
        }
        int r = m0 + g;
        size_t base0 = (size_t)(bb * LTOK + srcidx[r]) * C;
        size_t base1 = (size_t)(bb * LTOK + srcidx[r + 8]) * C;
        #pragma unroll
        for (int nt = 0; nt < 3; nt++) {
            int col = n0 + 8 * nt + 2 * cq;
            float2 x0 = *(const float2*)(x + base0 + col);
            float2 x1 = *(const float2*)(x + base1 + col);
            *(float2*)(g_ybuf + base0 + col) =
                make_float2(x0.x + acc[nt][0], x0.y + acc[nt][1]);
            *(float2*)(g_ybuf + base1 + col) =
                make_float2(x1.x + acc[nt][2], x1.y + acc[nt][3]);
        }
    }
}

// ======================= Kernel B: bf16 m16n8k16 MLP (R14/R16, unchanged) ==
#define SM_HID 0
#define SM_H2B 12544
#define SM_W1C 15872
#define SM_W2C 12544
#define B_TOT  22208

__global__ __launch_bounds__(512, 1)
void mlp_kernel(const float* __restrict__ g2, const float* __restrict__ b2,
                const float* __restrict__ w1, const float* __restrict__ bb1,
                const float* __restrict__ w2, const float* __restrict__ bb2,
                float* __restrict__ out)
{
    extern __shared__ float smf[];
    float* hid = smf + SM_HID;
    float* h2b = smf + SM_H2B;
    float* w1c = smf + SM_W1C;
    float* w2c = smf + SM_W2C;

    const int tid = threadIdx.x;
    const int t0 = blockIdx.x * NW;
    const int lane = tid & 31, wid = tid >> 5;
    const int g = lane >> 2, cq = lane & 3;

    const int w1p = tid >> 5, w1n = (tid & 31) * 12;
    float4 wpf[6];
    {
        const float* ra = w1 + (2 * w1p) * MLPH + w1n;
        const float* rb = w1 + (2 * w1p + 1) * MLPH + w1n;
        #pragma unroll
        for (int i = 0; i < 3; i++) wpf[i] = __ldg((const float4*)(ra + 4 * i));
        #pragma unroll
        for (int i = 0; i < 3; i++) wpf[3 + i] = __ldg((const float4*)(rb + 4 * i));
    }

    // ---- LN2 -> h2b[n][52] bf16x2 words
    {
        const int n = tid >> 3, q8 = tid & 7;
        const float* yr = g_ybuf + (size_t)(t0 + n) * C + q8 * 12;
        float v[12]; float s = 0.f, ss = 0.f;
        #pragma unroll
        for (int j = 0; j < 12; j++) { float t = yr[j]; v[j] = t; s += t; ss += t * t; }
        s  += __shfl_xor_sync(0xffffffffu, s, 1);  ss += __shfl_xor_sync(0xffffffffu, ss, 1);
        s  += __shfl_xor_sync(0xffffffffu, s, 2);  ss += __shfl_xor_sync(0xffffffffu, ss, 2);
        s  += __shfl_xor_sync(0xffffffffu, s, 4);  ss += __shfl_xor_sync(0xffffffffu, ss, 4);
        float mean = s * (1.f / 96.f);
        float var  = ss * (1.f / 96.f) - mean * mean;
        float rstd = rsqrtf(var + 1e-5f);
        float hv[12];
        #pragma unroll
        for (int j = 0; j < 12; j++) {
            int c = q8 * 12 + j;
            hv[j] = (v[j] - mean) * rstd * __ldg(g2 + c) + __ldg(b2 + c);
        }
        #pragma unroll
        for (int i = 0; i < 6; i += 2)
            stsb64(h2b + n * 52 + q8 * 6 + i,
                   pk2u(pkbf(hv[2 * i], hv[2 * i + 1]),
                        pkbf(hv[2 * i + 2], hv[2 * i + 3])));
    }

    // ---- GEMM1 (m16n8k16): warp = 2 m-tiles x 6 n-tiles
    const int mh = wid & 1, ng = wid >> 1;
    const int m0 = 32 * mh, n0 = 48 * ng;
    float acc1[2][6][4];
    #pragma unroll
    for (int nt = 0; nt < 6; nt++) {
        int col = n0 + 8 * nt + 2 * cq;
        float bx = __ldg(bb1 + col), by = __ldg(bb1 + col + 1);
        #pragma unroll
        for (int mi = 0; mi < 2; mi++) {
            acc1[mi][nt][0] = bx; acc1[mi][nt][1] = by;
            acc1[mi][nt][2] = bx; acc1[mi][nt][3] = by;
        }
    }
    {
        const float* ra = (const float*)wpf;
        const float* rb = (const float*)(wpf + 3);
        float* d = w1c + w1p * 396 + w1n;
        #pragma unroll
        for (int i = 0; i < 12; i += 2)
            stsb64(d + i, pk2u(pkbf(ra[i], rb[i]), pkbf(ra[i + 1], rb[i + 1])));
    }
    __syncthreads();

    #pragma unroll 1
    for (int c3 = 0; c3 < 3; c3++) {
        if (c3 < 2) {
            const float* ra = w1 + (32 * (c3 + 1) + 2 * w1p) * MLPH + w1n;
            const float* rb = ra + MLPH;
            #pragma unroll
            for (int i = 0; i < 3; i++) wpf[i] = __ldg((const float4*)(ra + 4 * i));
            #pragma unroll
            for (int i = 0; i < 3; i++) wpf[3 + i] = __ldg((const float4*)(rb + 4 * i));
        }
        #pragma unroll
        for (int kq = 0; kq < 2; kq++) {
            const int ploc = 8 * kq + 2 * cq;
            const int pA = 16 * c3 + ploc;
            unsigned A[2][4];
            #pragma unroll
            for (int mi = 0; mi < 2; mi++) {
                int row = m0 + 16 * mi + g;
                u64t lo = ldsb64(h2b + row * 52 + pA);
                u64t hi = ldsb64(h2b + (row + 8) * 52 + pA);
                A[mi][0] = (unsigned)lo; A[mi][2] = (unsigned)(lo >> 32);
                A[mi][1] = (unsigned)hi; A[mi][3] = (unsigned)(hi >> 32);
            }
            #pragma unroll
            for (int nt = 0; nt < 6; nt++) {
                const float* wp = w1c + ploc * 396 + n0 + 8 * nt + g;
                unsigned b0 = ldsu32(wp);
                unsigned b1 = ldsu32(wp + 396);
                mma16(acc1[0][nt], A[0], b0, b1);
                mma16(acc1[1][nt], A[1], b0, b1);
            }
        }
        __syncthreads();
        if (c3 < 2) {
            const float* ra = (const float*)wpf;
            const float* rb = (const float*)(wpf + 3);
            float* d = w1c + w1p * 396 + w1n;
            #pragma unroll
            for (int i = 0; i < 12; i += 2)
                stsb64(d + i, pk2u(pkbf(ra[i], rb[i]), pkbf(ra[i + 1], rb[i + 1])));
            __syncthreads();
        }
    }

    // GELU -> hid bf16x2
    #pragma unroll
    for (int mi = 0; mi < 2; mi++) {
        #pragma unroll
        for (int nt = 0; nt < 6; nt++) {
            int row = m0 + 16 * mi + g;
            int wrd = n0 / 2 + 4 * nt + cq;
            float* a = acc1[mi][nt];
            float g0 = 0.5f * a[0] * (1.0f + erff(a[0] * 0.70710678118654752f));
            float g1 = 0.5f * a[1] * (1.0f + erff(a[1] * 0.70710678118654752f));
            float g2v = 0.5f * a[2] * (1.0f + erff(a[2] * 0.70710678118654752f));
            float g3 = 0.5f * a[3] * (1.0f + erff(a[3] * 0.70710678118654752f));
            stsb32(hid + row * 196 + wrd, pkbf(g0, g1));
            stsb32(hid + (row + 8) * 196 + wrd, pkbf(g2v, g3));
        }
    }

    // ---- GEMM2 (m16n8k16): 6 chunks of 32 pairs
    const int mt = wid & 3, n3 = wid >> 2;
    const int m0b = 16 * mt, n0b = 24 * n3;
    float acc2[3][4];
    #pragma unroll
    for (int nt = 0; nt < 3; nt++) {
        int col = n0b + 8 * nt + 2 * cq;
        float bx = __ldg(bb2 + col), by = __ldg(bb2 + col + 1);
        acc2[nt][0] = bx; acc2[nt][1] = by;
        acc2[nt][2] = bx; acc2[nt][3] = by;
    }
    const int w2p = tid >> 4, w2n = (tid & 15) * 6;
    float2 wpf2[6];
    {
        const float* ra = w2 + (2 * w2p) * 96 + w2n;
        const float* rb = ra + 96;
        #pragma unroll
        for (int i = 0; i < 3; i++) wpf2[i] = __ldg((const float2*)(ra + 2 * i));
        #pragma unroll
        for (int i = 0; i < 3; i++) wpf2[3 + i] = __ldg((const float2*)(rb + 2 * i));
    }
    __syncthreads();

    #pragma unroll 1
    for (int ch = 0; ch < 6; ch++) {
        {
            const float* ra = (const float*)wpf2;
            const float* rb = (const float*)(wpf2 + 3);
            float* d = w2c + w2p * 100 + w2n;
            #pragma unroll
            for (int i = 0; i < 6; i += 2)
                stsb64(d + i, pk2u(pkbf(ra[i], rb[i]), pkbf(ra[i + 1], rb[i + 1])));
        }
        __syncthreads();
        if (ch < 5) {
            const float* ra = w2 + (64 * (ch + 1) + 2 * w2p) * 96 + w2n;
            const float* rb = ra + 96;
            #pragma unroll
            for (int i = 0; i < 3; i++) wpf2[i] = __ldg((const float2*)(ra + 2 * i));
            #pragma unroll
            for (int i = 0; i < 3; i++) wpf2[3 + i] = __ldg((const float2*)(rb + 2 * i));
        }
        #pragma unroll
        for (int kq = 0; kq < 4; kq++) {
            const int ploc = 8 * kq + 2 * cq;
            const int pA = 32 * ch + ploc;
            unsigned A[4];
            u64t lo = ldsb64(hid + (m0b + g) * 196 + pA);
            u64t hi = ldsb64(hid + (m0b + g + 8) * 196 + pA);
            A[0] = (unsigned)lo; A[2] = (unsigned)(lo >> 32);
            A[1] = (unsigned)hi; A[3] = (unsigned)(hi >> 32);
            #pragma unroll
            for (int nt = 0; nt < 3; nt++) {
                const float* wp = w2c + ploc * 100 + n0b + 8 * nt + g;
                unsigned b0 = ldsu32(wp);
                unsigned b1 = ldsu32(wp + 100);
                mma16(acc2[nt], A, b0, b1);
            }
        }
        __syncthreads();
    }

    // epilogue: residual + store
    #pragma unroll
    for (int nt = 0; nt < 3; nt++) {
        int col = n0b + 8 * nt + 2 * cq;
        int r0 = t0 + m0b + g;
        const float2 y0 = *(const float2*)(g_ybuf + (size_t)r0 * C + col);
        const float2 y1 = *(const float2*)(g_ybuf + (size_t)(r0 + 8) * C + col);
        float2 o0 = make_float2(y0.x + acc2[nt][0], y0.y + acc2[nt][1]);
        float2 o1 = make_float2(y1.x + acc2[nt][2], y1.y + acc2[nt][3]);
        *(float2*)(out + (size_t)r0 * C + col) = o0;
        *(float2*)(out + (size_t)(r0 + 8) * C + col) = o1;
    }
}

// ---------------------------------------------------------------------------
extern "C" void kernel_launch(void* const* d_in, const int* in_sizes, int n_in,
                              void* d_out, int out_size)
{
    const float* x        = (const float*)d_in[0];
    const float* norm1_g  = (const float*)d_in[1];
    const float* norm1_b  = (const float*)d_in[2];
    const float* qkv_w    = (const float*)d_in[3];
    const float* qkv_b    = (const float*)d_in[4];
    const float* proj_w   = (const float*)d_in[5];
    const float* proj_b   = (const float*)d_in[6];
    const float* bias_tab = (const float*)d_in[7];
    const float* norm2_g  = (const float*)d_in[8];
    const float* norm2_b  = (const float*)d_in[9];
    const float* mlp_w1   = (const float*)d_in[10];
    const float* mlp_b1   = (const float*)d_in[11];
    const float* mlp_w2   = (const float*)d_in[12];
    const float* mlp_b2   = (const float*)d_in[13];
    float* out = (float*)d_out;

    cudaFuncSetAttribute(win_attn_kernel,
                         cudaFuncAttributeMaxDynamicSharedMemorySize, A_TOT * 4);
    cudaFuncSetAttribute(mlp_kernel,
                         cudaFuncAttributeMaxDynamicSharedMemorySize, B_TOT * 4);

    win_attn_kernel<<<NTILE, 512, A_TOT * 4>>>(x, norm1_g, norm1_b,
                                               qkv_w, qkv_b, proj_w, proj_b,
                                               bias_tab);
    mlp_kernel<<<NTILE, 512, B_TOT * 4>>>(norm2_g, norm2_b,
                                          mlp_w1, mlp_b1, mlp_w2, mlp_b2, out);
}